// round 1
// baseline (speedup 1.0000x reference)
#include <cuda_runtime.h>
#include <cuda_bf16.h>
#include <math.h>

// ---------------- problem constants ----------------
#define NN      20000
#define INF_    256
#define HID     256
#define ZD      64
#define EP      120000      // positive edges
#define EN      600000      // negative edges (NEG*E)
#define ET      720000      // total scored edges
#define E2      240000      // directed encoder edges (2E)
#define LN_EPS  1e-5f

// ---------------- scratch (static device allocations are the sanctioned path) ----
__device__ float  g_M1[NN * 256];   // x@W1
__device__ float  g_A1[NN * 256];   // scatter accum layer1
__device__ float  g_H1[NN * 256];   // relu(LN(...))
__device__ float  g_M2[NN * 128];   // h1@[Wmu|Wlv]
__device__ float  g_A2[NN * 128];   // scatter accum mu|lv
__device__ float  g_Z [NN * 64];    // latent
__device__ float  g_M3[NN * 64];    // gemm scratch decoder
__device__ float  g_A3a[NN * 64];   // decoder accum pass1
__device__ float  g_A3b[NN * 64];   // decoder accum pass2
__device__ float  g_HD1[NN * 64];   // decoder hidden 1
__device__ float  g_HD2[NN * 64];   // decoder hidden 2 (= h)
__device__ float  g_P [NN * 128];   // [h@Wa1 | h@Wa2]
__device__ int    g_deg[NN];
__device__ float  g_dis[NN];
__device__ double g_acc[2];         // [0]=kl sum, [1]=recon sum (negated terms)

// ---------------- helpers ----------------
__device__ __forceinline__ void red4(float* p, float x, float y, float z, float w) {
    asm volatile("red.global.add.v4.f32 [%0], {%1,%2,%3,%4};"
                 :: "l"(p), "f"(x), "f"(y), "f"(z), "f"(w) : "memory");
}
__device__ __forceinline__ float logsig(float x) {
    // stable log(sigmoid(x))
    return fminf(x, 0.0f) - log1pf(expf(-fabsf(x)));
}

// ---------------- zero scratch ----------------
__global__ void zero_all() {
    size_t i = (size_t)blockIdx.x * blockDim.x + threadIdx.x;
    size_t st = (size_t)gridDim.x * blockDim.x;
    for (size_t k = i; k < (size_t)NN * 256; k += st) g_A1[k] = 0.f;
    for (size_t k = i; k < (size_t)NN * 128; k += st) g_A2[k] = 0.f;
    for (size_t k = i; k < (size_t)NN * 64;  k += st) { g_A3a[k] = 0.f; g_A3b[k] = 0.f; }
    for (size_t k = i; k < NN; k += st) g_deg[k] = 0;
    if (i == 0) { g_acc[0] = 0.0; g_acc[1] = 0.0; }
}

// ---------------- tiled fp32 GEMM: C[M,*] = A[M,Kin] @ W[Kin,*] ----------------
// block 256 threads, tile 64x64, BK=16, 4x4 microtile
__global__ void gemm64(const float* __restrict__ A, int lda,
                       const float* __restrict__ W, int ldw,
                       float* __restrict__ C, int ldc,
                       int M, int Kin) {
    __shared__ float As[16][68];
    __shared__ float Bs[16][68];
    int t  = threadIdx.x;
    int m0 = blockIdx.x * 64, n0 = blockIdx.y * 64;
    int ty = t >> 4, tx = t & 15;
    int la_m = t >> 2;        // 0..63
    int la_k = (t & 3) * 4;   // 0,4,8,12
    int lb_k = t >> 4;        // 0..15
    int lb_n = (t & 15) * 4;  // 0..60
    float acc[4][4];
#pragma unroll
    for (int i = 0; i < 4; i++)
#pragma unroll
        for (int j = 0; j < 4; j++) acc[i][j] = 0.f;

    for (int k0 = 0; k0 < Kin; k0 += 16) {
        float4 av = make_float4(0.f, 0.f, 0.f, 0.f);
        int gm = m0 + la_m;
        if (gm < M) av = *(const float4*)&A[(size_t)gm * lda + k0 + la_k];
        As[la_k + 0][la_m] = av.x; As[la_k + 1][la_m] = av.y;
        As[la_k + 2][la_m] = av.z; As[la_k + 3][la_m] = av.w;
        float4 bv = *(const float4*)&W[(size_t)(k0 + lb_k) * ldw + n0 + lb_n];
        *(float4*)&Bs[lb_k][lb_n] = bv;
        __syncthreads();
#pragma unroll
        for (int k = 0; k < 16; k++) {
            float4 a = *(const float4*)&As[k][ty * 4];
            float4 b = *(const float4*)&Bs[k][tx * 4];
            acc[0][0] += a.x * b.x; acc[0][1] += a.x * b.y; acc[0][2] += a.x * b.z; acc[0][3] += a.x * b.w;
            acc[1][0] += a.y * b.x; acc[1][1] += a.y * b.y; acc[1][2] += a.y * b.z; acc[1][3] += a.y * b.w;
            acc[2][0] += a.z * b.x; acc[2][1] += a.z * b.y; acc[2][2] += a.z * b.z; acc[2][3] += a.z * b.w;
            acc[3][0] += a.w * b.x; acc[3][1] += a.w * b.y; acc[3][2] += a.w * b.z; acc[3][3] += a.w * b.w;
        }
        __syncthreads();
    }
#pragma unroll
    for (int i = 0; i < 4; i++) {
        int gm = m0 + ty * 4 + i;
        if (gm < M)
            *(float4*)&C[(size_t)gm * ldc + n0 + tx * 4] =
                make_float4(acc[i][0], acc[i][1], acc[i][2], acc[i][3]);
    }
}

// ---------------- scatter-add: A[dst] += M[src], F floats (F4 = F/4) ------------
__global__ void scatter_add(const float* __restrict__ M, const int* __restrict__ src,
                            const int* __restrict__ dst, float* __restrict__ A,
                            int nE, int F4) {
    int gt = blockIdx.x * blockDim.x + threadIdx.x;
    int e = gt >> 5, lane = gt & 31;
    if (e >= nE) return;
    int s = src[e], d = dst[e];
    const float4* Mr = (const float4*)&M[(size_t)s * (F4 * 4)];
    float* Ar = &A[(size_t)d * (F4 * 4)];
    for (int c = lane; c < F4; c += 32) {
        float4 v = Mr[c];
        red4(Ar + c * 4, v.x, v.y, v.z, v.w);
    }
}

// ---------------- LayerNorm + ReLU, warp per row of 256 ----------------
__global__ void ln_relu(const float* __restrict__ A, const float* __restrict__ b,
                        const float* __restrict__ g, const float* __restrict__ bt,
                        float* __restrict__ H) {
    int w = (blockIdx.x * blockDim.x + threadIdx.x) >> 5;
    int lane = threadIdx.x & 31;
    if (w >= NN) return;
    float v[8];
    float s = 0.f;
#pragma unroll
    for (int i = 0; i < 8; i++) {
        int j = i * 32 + lane;
        v[i] = A[(size_t)w * 256 + j] + b[j];
        s += v[i];
    }
#pragma unroll
    for (int o = 16; o; o >>= 1) s += __shfl_xor_sync(0xffffffffu, s, o);
    float mu = s * (1.f / 256.f);
    float s2 = 0.f;
#pragma unroll
    for (int i = 0; i < 8; i++) { float d = v[i] - mu; s2 += d * d; }
#pragma unroll
    for (int o = 16; o; o >>= 1) s2 += __shfl_xor_sync(0xffffffffu, s2, o);
    float inv = rsqrtf(s2 * (1.f / 256.f) + LN_EPS);
#pragma unroll
    for (int i = 0; i < 8; i++) {
        int j = i * 32 + lane;
        H[(size_t)w * 256 + j] = fmaxf((v[i] - mu) * inv * g[j] + bt[j], 0.f);
    }
}

// ---------------- z = mu + eps*exp(0.5 lv); accumulate KL ----------------
__global__ void z_kl(const float* __restrict__ A2, const float* __restrict__ bmu,
                     const float* __restrict__ blv, const float* __restrict__ eps,
                     float* __restrict__ Z) {
    __shared__ float red[256];
    int idx = blockIdx.x * blockDim.x + threadIdx.x;
    float t = 0.f;
    if (idx < NN * 64) {
        int n = idx >> 6, j = idx & 63;
        float mu = A2[(size_t)n * 128 + j] + bmu[j];
        float lv = A2[(size_t)n * 128 + 64 + j] + blv[j];
        Z[idx] = mu + eps[idx] * expf(0.5f * lv);
        t = 1.f + lv - mu * mu - expf(lv);
    }
    red[threadIdx.x] = t;
    __syncthreads();
    for (int o = 128; o; o >>= 1) {
        if (threadIdx.x < o) red[threadIdx.x] += red[threadIdx.x + o];
        __syncthreads();
    }
    if (threadIdx.x == 0) atomicAdd(&g_acc[0], (double)red[0]);
}

// ---------------- decoder degree / dis ----------------
__global__ void deg_count(const int* __restrict__ pd) {
    int e = blockIdx.x * blockDim.x + threadIdx.x;
    if (e < EP) atomicAdd(&g_deg[pd[e]], 1);
}
__global__ void dis_kernel() {
    int n = blockIdx.x * blockDim.x + threadIdx.x;
    if (n < NN) g_dis[n] = rsqrtf((float)g_deg[n] + 1.0f);
}

// ---------------- normalized scatter over pos edges + self loops --------------
__global__ void scatter_norm(const float* __restrict__ M, const int* __restrict__ ps,
                             const int* __restrict__ pd, float* __restrict__ A) {
    int idx = blockIdx.x * blockDim.x + threadIdx.x;
    int e = idx >> 4, c = idx & 15;
    if (e >= EP + NN) return;
    int s, d; float coef;
    if (e < EP) { s = ps[e]; d = pd[e]; coef = g_dis[s] * g_dis[d]; }
    else        { s = d = e - EP; float x = g_dis[s]; coef = x * x; }
    float4 v = *(const float4*)&M[(size_t)s * 64 + c * 4];
    red4(&A[(size_t)d * 64 + c * 4], v.x * coef, v.y * coef, v.z * coef, v.w * coef);
}

__global__ void bias_relu(const float* __restrict__ A, const float* __restrict__ b,
                          float* __restrict__ H) {
    int idx = blockIdx.x * blockDim.x + threadIdx.x;
    if (idx < NN * 64) H[idx] = fmaxf(A[idx] + b[idx & 63], 0.f);
}

// ---------------- edge MLP + BCE (the hot kernel) ----------------
// tile: 64 edges x 64 hidden, K=128 ([|hu-hv|;hu*hv]); acc seeded with P1[u]+P2[v]
__global__ void edge_mlp(const float* __restrict__ h, const float* __restrict__ P,
                         const int* __restrict__ pos, const int* __restrict__ neg,
                         const float* __restrict__ Wa, const float* __restrict__ ba,
                         const float* __restrict__ Wb, const float* __restrict__ bb,
                         const float* __restrict__ tau) {
    extern __shared__ float sm[];
    float* Ws  = sm;                   // 128*68
    float* Ds  = Ws + 128 * 68;        // 128*68
    float* sba = Ds + 128 * 68;        // 64
    float* sWb = sba + 64;             // 64
    int*   su  = (int*)(sWb + 64);     // 64
    int*   sv  = su + 64;              // 64
    float* red = (float*)(sv + 64);    // 256

    int t = threadIdx.x;
    // stage weights: Ws[k][j] = Wa[(128+k)*64 + j], k in [0,128)
    for (int i = t; i < 128 * 64; i += 256) {
        int k = i >> 6, j = i & 63;
        Ws[k * 68 + j] = Wa[(size_t)(128 + k) * 64 + j];
    }
    if (t < 64) { sba[t] = ba[t]; sWb[t] = Wb[t]; }
    float tau_c = fmaxf(tau[0], 1e-4f);
    float bb0 = bb[0];
    int ty = t >> 4, tx = t & 15;
    float loc = 0.f;

    const int NTILES = ET / 64;   // 11250
    for (int tb = blockIdx.x; tb < NTILES; tb += gridDim.x) {
        int e0 = tb * 64;
        __syncthreads();                       // Ds/su/sv reuse barrier
        if (t < 64) {
            int e = e0 + t;
            if (e < EP) { su[t] = pos[e]; sv[t] = pos[EP + e]; }
            else        { su[t] = neg[e - EP]; sv[t] = neg[EN + (e - EP)]; }
        }
        __syncthreads();
        // build D features
        {
            int ee = t >> 2, part = t & 3;
            int u = su[ee], v = sv[ee];
            const float4* hu4 = (const float4*)&h[(size_t)u * 64];
            const float4* hv4 = (const float4*)&h[(size_t)v * 64];
#pragma unroll
            for (int q = 0; q < 4; q++) {
                float4 a = hu4[part * 4 + q];
                float4 b = hv4[part * 4 + q];
                int kk = part * 16 + q * 4;
                Ds[(kk + 0) * 68 + ee] = fabsf(a.x - b.x);
                Ds[(kk + 1) * 68 + ee] = fabsf(a.y - b.y);
                Ds[(kk + 2) * 68 + ee] = fabsf(a.z - b.z);
                Ds[(kk + 3) * 68 + ee] = fabsf(a.w - b.w);
                Ds[(64 + kk + 0) * 68 + ee] = a.x * b.x;
                Ds[(64 + kk + 1) * 68 + ee] = a.y * b.y;
                Ds[(64 + kk + 2) * 68 + ee] = a.z * b.z;
                Ds[(64 + kk + 3) * 68 + ee] = a.w * b.w;
            }
        }
        // seed acc with P1[u] + P2[v]
        float acc[4][4];
#pragma unroll
        for (int ee = 0; ee < 4; ee++) {
            int el = ty * 4 + ee;
            int u = su[el], v = sv[el];
            float4 p1 = *(const float4*)&P[(size_t)u * 128 + tx * 4];
            float4 p2 = *(const float4*)&P[(size_t)v * 128 + 64 + tx * 4];
            acc[ee][0] = p1.x + p2.x; acc[ee][1] = p1.y + p2.y;
            acc[ee][2] = p1.z + p2.z; acc[ee][3] = p1.w + p2.w;
        }
        __syncthreads();
#pragma unroll 4
        for (int k = 0; k < 128; k++) {
            float4 a = *(const float4*)&Ds[k * 68 + ty * 4];
            float4 b = *(const float4*)&Ws[k * 68 + tx * 4];
            acc[0][0] += a.x * b.x; acc[0][1] += a.x * b.y; acc[0][2] += a.x * b.z; acc[0][3] += a.x * b.w;
            acc[1][0] += a.y * b.x; acc[1][1] += a.y * b.y; acc[1][2] += a.y * b.z; acc[1][3] += a.y * b.w;
            acc[2][0] += a.z * b.x; acc[2][1] += a.z * b.y; acc[2][2] += a.z * b.z; acc[2][3] += a.z * b.w;
            acc[3][0] += a.w * b.x; acc[3][1] += a.w * b.y; acc[3][2] += a.w * b.z; acc[3][3] += a.w * b.w;
        }
        // epilogue: relu + Wb dot, reduce over tx (16 lanes), BCE
#pragma unroll
        for (int ee = 0; ee < 4; ee++) {
            float p = 0.f;
#pragma unroll
            for (int jj = 0; jj < 4; jj++) {
                int j = tx * 4 + jj;
                p += fmaxf(acc[ee][jj] + sba[j], 0.f) * sWb[j];
            }
#pragma unroll
            for (int o = 8; o; o >>= 1) p += __shfl_down_sync(0xffffffffu, p, o, 16);
            if (tx == 0) {
                float l = (p + bb0) / tau_c;
                int ge = e0 + ty * 4 + ee;
                loc += (ge < EP) ? (-5.0f * logsig(l)) : (-logsig(-l));
            }
        }
    }
    __syncthreads();
    red[t] = loc;
    __syncthreads();
    for (int o = 128; o; o >>= 1) {
        if (t < o) red[t] += red[t + o];
        __syncthreads();
    }
    if (t == 0) atomicAdd(&g_acc[1], (double)red[0]);
}

// ---------------- finalize ----------------
__global__ void finalize_k(float* out, int out_size) {
    double kl = -0.5 * g_acc[0] / (double)(NN * 64);
    double recon = g_acc[1] / (double)ET;
    if (out_size >= 3) {
        out[0] = (float)(recon + kl);
        out[1] = (float)recon;
        out[2] = (float)kl;
    } else {
        out[0] = (float)(recon + kl);
    }
}

// ---------------- launch ----------------
extern "C" void kernel_launch(void* const* d_in, const int* in_sizes, int n_in,
                              void* d_out, int out_size) {
    const float* x    = (const float*)d_in[0];
    const float* eps  = (const float*)d_in[1];
    const int* ei     = (const int*)d_in[2];     // [2, 2E]
    const int* pos    = (const int*)d_in[3];     // [2, E]
    const int* neg    = (const int*)d_in[4];     // [2, 5E]
    const float* W1   = (const float*)d_in[5];
    const float* b1   = (const float*)d_in[6];
    const float* g1   = (const float*)d_in[7];
    const float* bt1  = (const float*)d_in[8];
    const float* Wmu  = (const float*)d_in[9];
    const float* bmu  = (const float*)d_in[10];
    const float* Wlv  = (const float*)d_in[11];
    const float* blv  = (const float*)d_in[12];
    const float* Wd1  = (const float*)d_in[13];
    const float* bd1  = (const float*)d_in[14];
    const float* Wd2  = (const float*)d_in[15];
    const float* bd2  = (const float*)d_in[16];
    const float* Wa   = (const float*)d_in[17];
    const float* ba   = (const float*)d_in[18];
    const float* Wb   = (const float*)d_in[19];
    const float* bb   = (const float*)d_in[20];
    const float* tau  = (const float*)d_in[21];
    float* out = (float*)d_out;

    const int* src = ei;          // ei[0,:]
    const int* dst = ei + E2;     // ei[1,:]
    const int* ps  = pos;
    const int* pd  = pos + EP;

    // device symbol addresses (host side)
    float *M1, *A1, *H1, *M2, *A2, *Z, *M3, *A3a, *A3b, *HD1, *HD2, *Pm;
    cudaGetSymbolAddress((void**)&M1, g_M1);
    cudaGetSymbolAddress((void**)&A1, g_A1);
    cudaGetSymbolAddress((void**)&H1, g_H1);
    cudaGetSymbolAddress((void**)&M2, g_M2);
    cudaGetSymbolAddress((void**)&A2, g_A2);
    cudaGetSymbolAddress((void**)&Z,  g_Z);
    cudaGetSymbolAddress((void**)&M3, g_M3);
    cudaGetSymbolAddress((void**)&A3a, g_A3a);
    cudaGetSymbolAddress((void**)&A3b, g_A3b);
    cudaGetSymbolAddress((void**)&HD1, g_HD1);
    cudaGetSymbolAddress((void**)&HD2, g_HD2);
    cudaGetSymbolAddress((void**)&Pm, g_P);

    static int smem_set = 0;
    const int EDGE_SMEM = (128 * 68 * 2 + 64 * 2 + 64 * 2 + 256) * 4; // 71680 B
    cudaFuncSetAttribute(edge_mlp, cudaFuncAttributeMaxDynamicSharedMemorySize, EDGE_SMEM);
    (void)smem_set;

    zero_all<<<2048, 256>>>();

    dim3 g1d((NN + 63) / 64, 4);
    gemm64<<<g1d, 256>>>(x, 256, W1, 256, M1, 256, NN, 256);

    scatter_add<<<(E2 * 32 + 255) / 256, 256>>>(M1, src, dst, A1, E2, 64);
    ln_relu<<<(NN * 32 + 255) / 256, 256>>>(A1, b1, g1, bt1, H1);

    dim3 g2d((NN + 63) / 64, 1);
    gemm64<<<g2d, 256>>>(H1, 256, Wmu, 64, M2,      128, NN, 256);
    gemm64<<<g2d, 256>>>(H1, 256, Wlv, 64, M2 + 64, 128, NN, 256);
    scatter_add<<<(E2 * 32 + 255) / 256, 256>>>(M2, src, dst, A2, E2, 32);
    z_kl<<<(NN * 64 + 255) / 256, 256>>>(A2, bmu, blv, eps, Z);

    deg_count<<<(EP + 255) / 256, 256>>>(pd);
    dis_kernel<<<(NN + 255) / 256, 256>>>();

    gemm64<<<g2d, 256>>>(Z, 64, Wd1, 64, M3, 64, NN, 64);
    scatter_norm<<<((EP + NN) * 16 + 255) / 256, 256>>>(M3, ps, pd, A3a);
    bias_relu<<<(NN * 64 + 255) / 256, 256>>>(A3a, bd1, HD1);

    gemm64<<<g2d, 256>>>(HD1, 64, Wd2, 64, M3, 64, NN, 64);
    scatter_norm<<<((EP + NN) * 16 + 255) / 256, 256>>>(M3, ps, pd, A3b);
    bias_relu<<<(NN * 64 + 255) / 256, 256>>>(A3b, bd2, HD2);

    gemm64<<<g2d, 256>>>(HD2, 64, Wa,           64, Pm,      128, NN, 64);
    gemm64<<<g2d, 256>>>(HD2, 64, Wa + 64 * 64, 64, Pm + 64, 128, NN, 64);

    edge_mlp<<<444, 256, EDGE_SMEM>>>(HD2, Pm, pos, neg, Wa, ba, Wb, bb, tau);

    finalize_k<<<1, 1>>>(out, out_size);
}

// round 3
// speedup vs baseline: 1.3123x; 1.3123x over previous
#include <cuda_runtime.h>
#include <cuda_bf16.h>
#include <math.h>

// ---------------- problem constants ----------------
#define NN      20000
#define EP      120000      // positive edges
#define EN      600000      // negative edges (NEG*E)
#define ET      720000      // total scored edges
#define E2      240000      // directed encoder edges (2E)
#define LN_EPS  1e-5f

// ---------------- scratch ----------------
__device__ float  g_M1[NN * 256];   // x@W1
__device__ float  g_A1[NN * 256];   // scatter accum layer1
__device__ float  g_H1[NN * 256];   // relu(LN(...))
__device__ float  g_M2[NN * 128];   // h1@[Wmu|Wlv]
__device__ float  g_A2[NN * 128];   // scatter accum mu|lv
__device__ float  g_Z [NN * 64];    // latent
__device__ float  g_M3[NN * 64];    // gemm scratch decoder
__device__ float  g_A3a[NN * 64];   // decoder accum pass1
__device__ float  g_A3b[NN * 64];   // decoder accum pass2
__device__ float  g_HD1[NN * 64];   // decoder hidden 1
__device__ float  g_HD2[NN * 64];   // decoder hidden 2 (= h)
__device__ float  g_P [NN * 128];   // [h@Wa1 | h@Wa2]
__device__ int    g_deg[NN];
__device__ float  g_dis[NN];
__device__ double g_acc[2];         // [0]=kl sum, [1]=recon sum

// ---------------- helpers ----------------
__device__ __forceinline__ void red4(float* p, float x, float y, float z, float w) {
    asm volatile("red.global.add.v4.f32 [%0], {%1,%2,%3,%4};"
                 :: "l"(p), "f"(x), "f"(y), "f"(z), "f"(w) : "memory");
}
__device__ __forceinline__ float logsig(float x) {
    return fminf(x, 0.0f) - log1pf(expf(-fabsf(x)));
}
__device__ __forceinline__ unsigned f2tf32(float x) {
    unsigned r;
    asm("cvt.rna.tf32.f32 %0, %1;" : "=r"(r) : "f"(x));
    return r;
}
__device__ __forceinline__ void mma_tf32(float& d0, float& d1, float& d2, float& d3,
                                         unsigned a0, unsigned a1, unsigned a2, unsigned a3,
                                         unsigned b0, unsigned b1) {
    asm volatile("mma.sync.aligned.m16n8k8.row.col.f32.tf32.tf32.f32 "
                 "{%0,%1,%2,%3}, {%4,%5,%6,%7}, {%8,%9}, {%0,%1,%2,%3};"
                 : "+f"(d0), "+f"(d1), "+f"(d2), "+f"(d3)
                 : "r"(a0), "r"(a1), "r"(a2), "r"(a3), "r"(b0), "r"(b1));
}

// ---------------- zero scratch ----------------
__global__ void zero_all() {
    size_t i = (size_t)blockIdx.x * blockDim.x + threadIdx.x;
    size_t st = (size_t)gridDim.x * blockDim.x;
    for (size_t k = i; k < (size_t)NN * 256; k += st) g_A1[k] = 0.f;
    for (size_t k = i; k < (size_t)NN * 128; k += st) g_A2[k] = 0.f;
    for (size_t k = i; k < (size_t)NN * 64;  k += st) { g_A3a[k] = 0.f; g_A3b[k] = 0.f; }
    for (size_t k = i; k < NN; k += st) g_deg[k] = 0;
    if (i == 0) { g_acc[0] = 0.0; g_acc[1] = 0.0; }
}

// ---------------- tiled fp32 GEMM (unchanged, used for encoder/decoder) ---------
__global__ void gemm64(const float* __restrict__ A, int lda,
                       const float* __restrict__ W, int ldw,
                       float* __restrict__ C, int ldc,
                       int M, int Kin) {
    __shared__ float As[16][68];
    __shared__ float Bs[16][68];
    int t  = threadIdx.x;
    int m0 = blockIdx.x * 64, n0 = blockIdx.y * 64;
    int ty = t >> 4, tx = t & 15;
    int la_m = t >> 2;
    int la_k = (t & 3) * 4;
    int lb_k = t >> 4;
    int lb_n = (t & 15) * 4;
    float acc[4][4];
#pragma unroll
    for (int i = 0; i < 4; i++)
#pragma unroll
        for (int j = 0; j < 4; j++) acc[i][j] = 0.f;

    for (int k0 = 0; k0 < Kin; k0 += 16) {
        float4 av = make_float4(0.f, 0.f, 0.f, 0.f);
        int gm = m0 + la_m;
        if (gm < M) av = *(const float4*)&A[(size_t)gm * lda + k0 + la_k];
        As[la_k + 0][la_m] = av.x; As[la_k + 1][la_m] = av.y;
        As[la_k + 2][la_m] = av.z; As[la_k + 3][la_m] = av.w;
        float4 bv = *(const float4*)&W[(size_t)(k0 + lb_k) * ldw + n0 + lb_n];
        *(float4*)&Bs[lb_k][lb_n] = bv;
        __syncthreads();
#pragma unroll
        for (int k = 0; k < 16; k++) {
            float4 a = *(const float4*)&As[k][ty * 4];
            float4 b = *(const float4*)&Bs[k][tx * 4];
            acc[0][0] += a.x * b.x; acc[0][1] += a.x * b.y; acc[0][2] += a.x * b.z; acc[0][3] += a.x * b.w;
            acc[1][0] += a.y * b.x; acc[1][1] += a.y * b.y; acc[1][2] += a.y * b.z; acc[1][3] += a.y * b.w;
            acc[2][0] += a.z * b.x; acc[2][1] += a.z * b.y; acc[2][2] += a.z * b.z; acc[2][3] += a.z * b.w;
            acc[3][0] += a.w * b.x; acc[3][1] += a.w * b.y; acc[3][2] += a.w * b.z; acc[3][3] += a.w * b.w;
        }
        __syncthreads();
    }
#pragma unroll
    for (int i = 0; i < 4; i++) {
        int gm = m0 + ty * 4 + i;
        if (gm < M)
            *(float4*)&C[(size_t)gm * ldc + n0 + tx * 4] =
                make_float4(acc[i][0], acc[i][1], acc[i][2], acc[i][3]);
    }
}

// ---------------- scatter-add ----------------
__global__ void scatter_add(const float* __restrict__ M, const int* __restrict__ src,
                            const int* __restrict__ dst, float* __restrict__ A,
                            int nE, int F4) {
    int gt = blockIdx.x * blockDim.x + threadIdx.x;
    int e = gt >> 5, lane = gt & 31;
    if (e >= nE) return;
    int s = src[e], d = dst[e];
    const float4* Mr = (const float4*)&M[(size_t)s * (F4 * 4)];
    float* Ar = &A[(size_t)d * (F4 * 4)];
    for (int c = lane; c < F4; c += 32) {
        float4 v = Mr[c];
        red4(Ar + c * 4, v.x, v.y, v.z, v.w);
    }
}

// ---------------- LayerNorm + ReLU ----------------
__global__ void ln_relu(const float* __restrict__ A, const float* __restrict__ b,
                        const float* __restrict__ g, const float* __restrict__ bt,
                        float* __restrict__ H) {
    int w = (blockIdx.x * blockDim.x + threadIdx.x) >> 5;
    int lane = threadIdx.x & 31;
    if (w >= NN) return;
    float v[8];
    float s = 0.f;
#pragma unroll
    for (int i = 0; i < 8; i++) {
        int j = i * 32 + lane;
        v[i] = A[(size_t)w * 256 + j] + b[j];
        s += v[i];
    }
#pragma unroll
    for (int o = 16; o; o >>= 1) s += __shfl_xor_sync(0xffffffffu, s, o);
    float mu = s * (1.f / 256.f);
    float s2 = 0.f;
#pragma unroll
    for (int i = 0; i < 8; i++) { float d = v[i] - mu; s2 += d * d; }
#pragma unroll
    for (int o = 16; o; o >>= 1) s2 += __shfl_xor_sync(0xffffffffu, s2, o);
    float inv = rsqrtf(s2 * (1.f / 256.f) + LN_EPS);
#pragma unroll
    for (int i = 0; i < 8; i++) {
        int j = i * 32 + lane;
        H[(size_t)w * 256 + j] = fmaxf((v[i] - mu) * inv * g[j] + bt[j], 0.f);
    }
}

// ---------------- z = mu + eps*exp(0.5 lv); accumulate KL ----------------
__global__ void z_kl(const float* __restrict__ A2, const float* __restrict__ bmu,
                     const float* __restrict__ blv, const float* __restrict__ eps,
                     float* __restrict__ Z) {
    __shared__ float red[256];
    int idx = blockIdx.x * blockDim.x + threadIdx.x;
    float t = 0.f;
    if (idx < NN * 64) {
        int n = idx >> 6, j = idx & 63;
        float mu = A2[(size_t)n * 128 + j] + bmu[j];
        float lv = A2[(size_t)n * 128 + 64 + j] + blv[j];
        Z[idx] = mu + eps[idx] * expf(0.5f * lv);
        t = 1.f + lv - mu * mu - expf(lv);
    }
    red[threadIdx.x] = t;
    __syncthreads();
    for (int o = 128; o; o >>= 1) {
        if (threadIdx.x < o) red[threadIdx.x] += red[threadIdx.x + o];
        __syncthreads();
    }
    if (threadIdx.x == 0) atomicAdd(&g_acc[0], (double)red[0]);
}

// ---------------- decoder degree / dis ----------------
__global__ void deg_count(const int* __restrict__ pd) {
    int e = blockIdx.x * blockDim.x + threadIdx.x;
    if (e < EP) atomicAdd(&g_deg[pd[e]], 1);
}
__global__ void dis_kernel() {
    int n = blockIdx.x * blockDim.x + threadIdx.x;
    if (n < NN) g_dis[n] = rsqrtf((float)g_deg[n] + 1.0f);
}

// ---------------- normalized scatter ----------------
__global__ void scatter_norm(const float* __restrict__ M, const int* __restrict__ ps,
                             const int* __restrict__ pd, float* __restrict__ A) {
    int idx = blockIdx.x * blockDim.x + threadIdx.x;
    int e = idx >> 4, c = idx & 15;
    if (e >= EP + NN) return;
    int s, d; float coef;
    if (e < EP) { s = ps[e]; d = pd[e]; coef = g_dis[s] * g_dis[d]; }
    else        { s = d = e - EP; float x = g_dis[s]; coef = x * x; }
    float4 v = *(const float4*)&M[(size_t)s * 64 + c * 4];
    red4(&A[(size_t)d * 64 + c * 4], v.x * coef, v.y * coef, v.z * coef, v.w * coef);
}

__global__ void bias_relu(const float* __restrict__ A, const float* __restrict__ b,
                          float* __restrict__ H) {
    int idx = blockIdx.x * blockDim.x + threadIdx.x;
    if (idx < NN * 64) H[idx] = fmaxf(A[idx] + b[idx & 63], 0.f);
}

// ---------------- edge MLP + BCE via tf32 tensor cores ----------------
// Tile: 64 edges x 64 hidden, K=128 features ([|hu-hv|; hu*hv]).
// acc seeded with P1[u]+P2[v] (linear hu/hv parts factored out per-node).
// smem strides: Ds 132 (conflict-free A-frag reads), Ws 72 (conflict-free B-frag reads)
#define DS_S 132
#define WS_S 72
__global__ void edge_mlp_tc(const float* __restrict__ h, const float* __restrict__ P,
                            const int* __restrict__ pos, const int* __restrict__ neg,
                            const float* __restrict__ Wa, const float* __restrict__ ba,
                            const float* __restrict__ Wb, const float* __restrict__ bb,
                            const float* __restrict__ tau) {
    extern __shared__ float sm[];
    float* Ws   = sm;                    // [128][WS_S] tf32 weights
    float* Ds   = Ws + 128 * WS_S;       // [64][DS_S] tf32 features
    float* sba  = Ds + 64 * DS_S;        // 64
    float* sWb  = sba + 64;              // 64
    float* slog = sWb + 64;              // 64 per-edge logits accum
    float* red  = slog + 64;             // 256
    int*   su   = (int*)(red + 256);     // 64
    int*   sv   = su + 64;               // 64

    int t = threadIdx.x;
    int w = t >> 5, lane = t & 31;
    int g = lane >> 2, t4 = lane & 3;
    int r0 = (w & 3) * 16;               // edge-row block of this warp
    int n0 = (w >> 2) * 32;              // col block of this warp

    // stage tf32 weights: Ws[k][j] = tf32(Wa[(128+k)*64 + j])
    for (int i = t; i < 128 * 64; i += 256) {
        int k = i >> 6, j = i & 63;
        Ws[k * WS_S + j] = __uint_as_float(f2tf32(Wa[(size_t)(128 + k) * 64 + j]));
    }
    if (t < 64) { sba[t] = ba[t]; sWb[t] = Wb[t]; }
    float tau_c = fmaxf(tau[0], 1e-4f);
    float bb0 = bb[0];
    float loc = 0.f;

    const int NTILES = ET / 64;          // 11250
    for (int tb = blockIdx.x; tb < NTILES; tb += gridDim.x) {
        int e0 = tb * 64;
        __syncthreads();                 // protect Ds/su/sv/slog from prev iter readers
        if (t < 64) {
            int e = e0 + t;
            if (e < EP) { su[t] = pos[e]; sv[t] = pos[EP + e]; }
            else        { su[t] = neg[e - EP]; sv[t] = neg[EN + (e - EP)]; }
            slog[t] = 0.f;
        }
        __syncthreads();

        // build tf32 feature tile Ds[edge][k]
        {
            int ee = t >> 2, part = t & 3;
            int u = su[ee], v = sv[ee];
            const float4* hu4 = (const float4*)&h[(size_t)u * 64];
            const float4* hv4 = (const float4*)&h[(size_t)v * 64];
#pragma unroll
            for (int q = 0; q < 4; q++) {
                float4 a = hu4[part * 4 + q];
                float4 b = hv4[part * 4 + q];
                int kk = part * 16 + q * 4;
                float4 dv, pv;
                dv.x = __uint_as_float(f2tf32(fabsf(a.x - b.x)));
                dv.y = __uint_as_float(f2tf32(fabsf(a.y - b.y)));
                dv.z = __uint_as_float(f2tf32(fabsf(a.z - b.z)));
                dv.w = __uint_as_float(f2tf32(fabsf(a.w - b.w)));
                pv.x = __uint_as_float(f2tf32(a.x * b.x));
                pv.y = __uint_as_float(f2tf32(a.y * b.y));
                pv.z = __uint_as_float(f2tf32(a.z * b.z));
                pv.w = __uint_as_float(f2tf32(a.w * b.w));
                *(float4*)&Ds[ee * DS_S + kk] = dv;
                *(float4*)&Ds[ee * DS_S + 64 + kk] = pv;
            }
        }

        // seed acc with P1[u] + P2[v] at this thread's C-fragment coords
        float acc[4][4];
        {
            int uA = su[r0 + g],     vA = sv[r0 + g];
            int uB = su[r0 + g + 8], vB = sv[r0 + g + 8];
#pragma unroll
            for (int s = 0; s < 4; s++) {
                int j0 = n0 + s * 8 + t4 * 2;
                float2 p1 = *(const float2*)&P[(size_t)uA * 128 + j0];
                float2 p2 = *(const float2*)&P[(size_t)vA * 128 + 64 + j0];
                acc[s][0] = p1.x + p2.x; acc[s][1] = p1.y + p2.y;
                float2 q1 = *(const float2*)&P[(size_t)uB * 128 + j0];
                float2 q2 = *(const float2*)&P[(size_t)vB * 128 + 64 + j0];
                acc[s][2] = q1.x + q2.x; acc[s][3] = q1.y + q2.y;
            }
        }
        __syncthreads();                 // Ds complete

        // K loop: 16 steps of k=8
#pragma unroll 4
        for (int ks = 0; ks < 16; ks++) {
            int k0 = ks * 8;
            unsigned a0 = __float_as_uint(Ds[(r0 + g) * DS_S + k0 + t4]);
            unsigned a1 = __float_as_uint(Ds[(r0 + g + 8) * DS_S + k0 + t4]);
            unsigned a2 = __float_as_uint(Ds[(r0 + g) * DS_S + k0 + t4 + 4]);
            unsigned a3 = __float_as_uint(Ds[(r0 + g + 8) * DS_S + k0 + t4 + 4]);
#pragma unroll
            for (int s = 0; s < 4; s++) {
                int n = n0 + s * 8 + g;
                unsigned b0 = __float_as_uint(Ws[(k0 + t4) * WS_S + n]);
                unsigned b1 = __float_as_uint(Ws[(k0 + t4 + 4) * WS_S + n]);
                mma_tf32(acc[s][0], acc[s][1], acc[s][2], acc[s][3],
                         a0, a1, a2, a3, b0, b1);
            }
        }

        // epilogue: relu + dot Wb; per-row partials, 4-lane shfl reduce, smem atomics
        {
            float p_lo = 0.f, p_hi = 0.f;
#pragma unroll
            for (int s = 0; s < 4; s++) {
                int j0 = n0 + s * 8 + t4 * 2;
                p_lo += fmaxf(acc[s][0] + sba[j0], 0.f) * sWb[j0]
                      + fmaxf(acc[s][1] + sba[j0 + 1], 0.f) * sWb[j0 + 1];
                p_hi += fmaxf(acc[s][2] + sba[j0], 0.f) * sWb[j0]
                      + fmaxf(acc[s][3] + sba[j0 + 1], 0.f) * sWb[j0 + 1];
            }
            p_lo += __shfl_down_sync(0xffffffffu, p_lo, 2, 4);
            p_lo += __shfl_down_sync(0xffffffffu, p_lo, 1, 4);
            p_hi += __shfl_down_sync(0xffffffffu, p_hi, 2, 4);
            p_hi += __shfl_down_sync(0xffffffffu, p_hi, 1, 4);
            if (t4 == 0) {
                atomicAdd(&slog[r0 + g], p_lo);
                atomicAdd(&slog[r0 + g + 8], p_hi);
            }
        }
        __syncthreads();

        if (t < 64) {
            float l = (slog[t] + bb0) / tau_c;
            int ge = e0 + t;
            loc += (ge < EP) ? (-5.0f * logsig(l)) : (-logsig(-l));
        }
    }
    __syncthreads();
    red[t] = loc;
    __syncthreads();
    for (int o = 128; o; o >>= 1) {
        if (t < o) red[t] += red[t + o];
        __syncthreads();
    }
    if (t == 0) atomicAdd(&g_acc[1], (double)red[0]);
}

// ---------------- finalize ----------------
__global__ void finalize_k(float* out, int out_size) {
    double kl = -0.5 * g_acc[0] / (double)(NN * 64);
    double recon = g_acc[1] / (double)ET;
    if (out_size >= 3) {
        out[0] = (float)(recon + kl);
        out[1] = (float)recon;
        out[2] = (float)kl;
    } else {
        out[0] = (float)(recon + kl);
    }
}

// ---------------- launch ----------------
extern "C" void kernel_launch(void* const* d_in, const int* in_sizes, int n_in,
                              void* d_out, int out_size) {
    const float* x    = (const float*)d_in[0];
    const float* eps  = (const float*)d_in[1];
    const int* ei     = (const int*)d_in[2];
    const int* pos    = (const int*)d_in[3];
    const int* neg    = (const int*)d_in[4];
    const float* W1   = (const float*)d_in[5];
    const float* b1   = (const float*)d_in[6];
    const float* g1   = (const float*)d_in[7];
    const float* bt1  = (const float*)d_in[8];
    const float* Wmu  = (const float*)d_in[9];
    const float* bmu  = (const float*)d_in[10];
    const float* Wlv  = (const float*)d_in[11];
    const float* blv  = (const float*)d_in[12];
    const float* Wd1  = (const float*)d_in[13];
    const float* bd1  = (const float*)d_in[14];
    const float* Wd2  = (const float*)d_in[15];
    const float* bd2  = (const float*)d_in[16];
    const float* Wa   = (const float*)d_in[17];
    const float* ba   = (const float*)d_in[18];
    const float* Wb   = (const float*)d_in[19];
    const float* bb   = (const float*)d_in[20];
    const float* tau  = (const float*)d_in[21];
    float* out = (float*)d_out;

    const int* src = ei;
    const int* dst = ei + E2;
    const int* ps  = pos;
    const int* pd  = pos + EP;

    float *M1, *A1, *H1, *M2, *A2, *Z, *M3, *A3a, *A3b, *HD1, *HD2, *Pm;
    cudaGetSymbolAddress((void**)&M1, g_M1);
    cudaGetSymbolAddress((void**)&A1, g_A1);
    cudaGetSymbolAddress((void**)&H1, g_H1);
    cudaGetSymbolAddress((void**)&M2, g_M2);
    cudaGetSymbolAddress((void**)&A2, g_A2);
    cudaGetSymbolAddress((void**)&Z,  g_Z);
    cudaGetSymbolAddress((void**)&M3, g_M3);
    cudaGetSymbolAddress((void**)&A3a, g_A3a);
    cudaGetSymbolAddress((void**)&A3b, g_A3b);
    cudaGetSymbolAddress((void**)&HD1, g_HD1);
    cudaGetSymbolAddress((void**)&HD2, g_HD2);
    cudaGetSymbolAddress((void**)&Pm, g_P);

    const int EDGE_SMEM = (128 * WS_S + 64 * DS_S + 64 * 3 + 256 + 128) * 4;
    cudaFuncSetAttribute(edge_mlp_tc, cudaFuncAttributeMaxDynamicSharedMemorySize, EDGE_SMEM);

    zero_all<<<2048, 256>>>();

    dim3 g1d((NN + 63) / 64, 4);
    gemm64<<<g1d, 256>>>(x, 256, W1, 256, M1, 256, NN, 256);

    scatter_add<<<(E2 * 32 + 255) / 256, 256>>>(M1, src, dst, A1, E2, 64);
    ln_relu<<<(NN * 32 + 255) / 256, 256>>>(A1, b1, g1, bt1, H1);

    dim3 g2d((NN + 63) / 64, 1);
    gemm64<<<g2d, 256>>>(H1, 256, Wmu, 64, M2,      128, NN, 256);
    gemm64<<<g2d, 256>>>(H1, 256, Wlv, 64, M2 + 64, 128, NN, 256);
    scatter_add<<<(E2 * 32 + 255) / 256, 256>>>(M2, src, dst, A2, E2, 32);
    z_kl<<<(NN * 64 + 255) / 256, 256>>>(A2, bmu, blv, eps, Z);

    deg_count<<<(EP + 255) / 256, 256>>>(pd);
    dis_kernel<<<(NN + 255) / 256, 256>>>();

    gemm64<<<g2d, 256>>>(Z, 64, Wd1, 64, M3, 64, NN, 64);
    scatter_norm<<<((EP + NN) * 16 + 255) / 256, 256>>>(M3, ps, pd, A3a);
    bias_relu<<<(NN * 64 + 255) / 256, 256>>>(A3a, bd1, HD1);

    gemm64<<<g2d, 256>>>(HD1, 64, Wd2, 64, M3, 64, NN, 64);
    scatter_norm<<<((EP + NN) * 16 + 255) / 256, 256>>>(M3, ps, pd, A3b);
    bias_relu<<<(NN * 64 + 255) / 256, 256>>>(A3b, bd2, HD2);

    gemm64<<<g2d, 256>>>(HD2, 64, Wa,           64, Pm,      128, NN, 64);
    gemm64<<<g2d, 256>>>(HD2, 64, Wa + 64 * 64, 64, Pm + 64, 128, NN, 64);

    edge_mlp_tc<<<444, 256, EDGE_SMEM>>>(HD2, Pm, pos, neg, Wa, ba, Wb, bb, tau);

    finalize_k<<<1, 1>>>(out, out_size);
}

// round 5
// speedup vs baseline: 1.5436x; 1.1763x over previous
#include <cuda_runtime.h>
#include <cuda_bf16.h>
#include <math.h>

// ---------------- problem constants ----------------
#define NN      20000
#define EP      120000      // positive edges
#define EN      600000      // negative edges (NEG*E)
#define ET      720000      // total scored edges
#define E2      240000      // directed encoder edges (2E)
#define LN_EPS  1e-5f

// ---------------- scratch ----------------
__device__ float  g_M1[NN * 256];   // x@W1
__device__ float  g_A1[NN * 256];   // scatter accum layer1
__device__ float  g_H1[NN * 256];   // relu(LN(...))
__device__ float  g_M2[NN * 128];   // h1@[Wmu|Wlv]
__device__ float  g_A2[NN * 128];   // scatter accum mu|lv
__device__ float  g_Z [NN * 64];    // latent
__device__ float  g_M3[NN * 64];    // gemm scratch decoder
__device__ float  g_A3a[NN * 64];   // decoder accum pass1
__device__ float  g_A3b[NN * 64];   // decoder accum pass2
__device__ float  g_HD1[NN * 64];   // decoder hidden 1
__device__ float  g_HD2[NN * 64];   // decoder hidden 2 (= h)
__device__ float  g_P [NN * 128];   // [h@Wa1 | h@Wa2]
__device__ int    g_deg[NN];
__device__ float  g_dis[NN];
__device__ double g_acc[2];         // [0]=kl sum, [1]=recon sum

// ---------------- helpers ----------------
__device__ __forceinline__ void red4(float* p, float x, float y, float z, float w) {
    asm volatile("red.global.add.v4.f32 [%0], {%1,%2,%3,%4};"
                 :: "l"(p), "f"(x), "f"(y), "f"(z), "f"(w) : "memory");
}
__device__ __forceinline__ float logsig(float x) {
    return fminf(x, 0.0f) - log1pf(expf(-fabsf(x)));
}
__device__ __forceinline__ unsigned f2tf32(float x) {
    unsigned r;
    asm("cvt.rna.tf32.f32 %0, %1;" : "=r"(r) : "f"(x));
    return r;
}
__device__ __forceinline__ void mma_tf32(float& d0, float& d1, float& d2, float& d3,
                                         unsigned a0, unsigned a1, unsigned a2, unsigned a3,
                                         unsigned b0, unsigned b1) {
    asm volatile("mma.sync.aligned.m16n8k8.row.col.f32.tf32.tf32.f32 "
                 "{%0,%1,%2,%3}, {%4,%5,%6,%7}, {%8,%9}, {%0,%1,%2,%3};"
                 : "+f"(d0), "+f"(d1), "+f"(d2), "+f"(d3)
                 : "r"(a0), "r"(a1), "r"(a2), "r"(a3), "r"(b0), "r"(b1));
}

// ---------------- zero scratch ----------------
__global__ void zero_all() {
    size_t i = (size_t)blockIdx.x * blockDim.x + threadIdx.x;
    size_t st = (size_t)gridDim.x * blockDim.x;
    for (size_t k = i; k < (size_t)NN * 256; k += st) g_A1[k] = 0.f;
    for (size_t k = i; k < (size_t)NN * 128; k += st) g_A2[k] = 0.f;
    for (size_t k = i; k < (size_t)NN * 64;  k += st) { g_A3a[k] = 0.f; g_A3b[k] = 0.f; }
    for (size_t k = i; k < NN; k += st) g_deg[k] = 0;
    if (i == 0) { g_acc[0] = 0.0; g_acc[1] = 0.0; }
}

// ---------------- tf32 tensor-core GEMM: C[M,N] = A[M,K] @ W[K,N] -------------
// block 256 (8 warps): tile 64x64. warp w: rows (w&3)*16..+16, cols (w>>2)*32..+32
// m16n8k8; As[64][36], Ws[32][72] conflict-free for fragment patterns.
#define AS_S 36
#define WSG_S 72
__global__ void gemm_tf32(const float* __restrict__ A, int lda,
                          const float* __restrict__ W, int ldw,
                          float* __restrict__ C, int ldc,
                          int M, int Kin) {
    __shared__ float As[64 * AS_S];
    __shared__ float Ws[32 * WSG_S];
    int t = threadIdx.x;
    int w = t >> 5, lane = t & 31;
    int g = lane >> 2, t4 = lane & 3;
    int r0 = (w & 3) * 16;
    int n0 = (w >> 2) * 32;
    int m0 = blockIdx.x * 64, nb = blockIdx.y * 64;

    // A-load coords: row = t>>2 (0..63), k-base = (t&3)*8
    int ar = t >> 2, ak = (t & 3) * 8;
    // W-load coords: k-row = t>>3 (0..31), col-base = (t&7)*8
    int wk = t >> 3, wn = (t & 7) * 8;

    float acc[4][4];
#pragma unroll
    for (int s = 0; s < 4; s++)
#pragma unroll
        for (int j = 0; j < 4; j++) acc[s][j] = 0.f;

    for (int k0 = 0; k0 < Kin; k0 += 32) {
        // stage A tile (convert to tf32)
        {
            int gm = m0 + ar;
            float4 v0 = make_float4(0.f,0.f,0.f,0.f), v1 = v0;
            if (gm < M) {
                const float* ap = &A[(size_t)gm * lda + k0 + ak];
                v0 = *(const float4*)ap;
                v1 = *(const float4*)(ap + 4);
            }
            float* d = &As[ar * AS_S + ak];
            d[0] = __uint_as_float(f2tf32(v0.x)); d[1] = __uint_as_float(f2tf32(v0.y));
            d[2] = __uint_as_float(f2tf32(v0.z)); d[3] = __uint_as_float(f2tf32(v0.w));
            d[4] = __uint_as_float(f2tf32(v1.x)); d[5] = __uint_as_float(f2tf32(v1.y));
            d[6] = __uint_as_float(f2tf32(v1.z)); d[7] = __uint_as_float(f2tf32(v1.w));
        }
        // stage W tile
        {
            const float* wp = &W[(size_t)(k0 + wk) * ldw + nb + wn];
            float4 v0 = *(const float4*)wp;
            float4 v1 = *(const float4*)(wp + 4);
            float* d = &Ws[wk * WSG_S + wn];
            d[0] = __uint_as_float(f2tf32(v0.x)); d[1] = __uint_as_float(f2tf32(v0.y));
            d[2] = __uint_as_float(f2tf32(v0.z)); d[3] = __uint_as_float(f2tf32(v0.w));
            d[4] = __uint_as_float(f2tf32(v1.x)); d[5] = __uint_as_float(f2tf32(v1.y));
            d[6] = __uint_as_float(f2tf32(v1.z)); d[7] = __uint_as_float(f2tf32(v1.w));
        }
        __syncthreads();
#pragma unroll
        for (int ks = 0; ks < 4; ks++) {
            int kk = ks * 8;
            unsigned a0 = __float_as_uint(As[(r0 + g) * AS_S + kk + t4]);
            unsigned a1 = __float_as_uint(As[(r0 + g + 8) * AS_S + kk + t4]);
            unsigned a2 = __float_as_uint(As[(r0 + g) * AS_S + kk + t4 + 4]);
            unsigned a3 = __float_as_uint(As[(r0 + g + 8) * AS_S + kk + t4 + 4]);
#pragma unroll
            for (int s = 0; s < 4; s++) {
                int n = n0 + s * 8 + g;
                unsigned b0 = __float_as_uint(Ws[(kk + t4) * WSG_S + n]);
                unsigned b1 = __float_as_uint(Ws[(kk + t4 + 4) * WSG_S + n]);
                mma_tf32(acc[s][0], acc[s][1], acc[s][2], acc[s][3],
                         a0, a1, a2, a3, b0, b1);
            }
        }
        __syncthreads();
    }
    // store C fragments
    int gmA = m0 + r0 + g, gmB = gmA + 8;
#pragma unroll
    for (int s = 0; s < 4; s++) {
        int cn = nb + n0 + s * 8 + t4 * 2;
        if (gmA < M) *(float2*)&C[(size_t)gmA * ldc + cn] = make_float2(acc[s][0], acc[s][1]);
        if (gmB < M) *(float2*)&C[(size_t)gmB * ldc + cn] = make_float2(acc[s][2], acc[s][3]);
    }
}

// ---------------- scatter-add ----------------
__global__ void scatter_add(const float* __restrict__ M, const int* __restrict__ src,
                            const int* __restrict__ dst, float* __restrict__ A,
                            int nE, int F4) {
    int gt = blockIdx.x * blockDim.x + threadIdx.x;
    int e = gt >> 5, lane = gt & 31;
    if (e >= nE) return;
    int s = src[e], d = dst[e];
    const float4* Mr = (const float4*)&M[(size_t)s * (F4 * 4)];
    float* Ar = &A[(size_t)d * (F4 * 4)];
    for (int c = lane; c < F4; c += 32) {
        float4 v = Mr[c];
        red4(Ar + c * 4, v.x, v.y, v.z, v.w);
    }
}

// ---------------- LayerNorm + ReLU ----------------
__global__ void ln_relu(const float* __restrict__ A, const float* __restrict__ b,
                        const float* __restrict__ g, const float* __restrict__ bt,
                        float* __restrict__ H) {
    int w = (blockIdx.x * blockDim.x + threadIdx.x) >> 5;
    int lane = threadIdx.x & 31;
    if (w >= NN) return;
    float v[8];
    float s = 0.f;
#pragma unroll
    for (int i = 0; i < 8; i++) {
        int j = i * 32 + lane;
        v[i] = A[(size_t)w * 256 + j] + b[j];
        s += v[i];
    }
#pragma unroll
    for (int o = 16; o; o >>= 1) s += __shfl_xor_sync(0xffffffffu, s, o);
    float mu = s * (1.f / 256.f);
    float s2 = 0.f;
#pragma unroll
    for (int i = 0; i < 8; i++) { float d = v[i] - mu; s2 += d * d; }
#pragma unroll
    for (int o = 16; o; o >>= 1) s2 += __shfl_xor_sync(0xffffffffu, s2, o);
    float inv = rsqrtf(s2 * (1.f / 256.f) + LN_EPS);
#pragma unroll
    for (int i = 0; i < 8; i++) {
        int j = i * 32 + lane;
        H[(size_t)w * 256 + j] = fmaxf((v[i] - mu) * inv * g[j] + bt[j], 0.f);
    }
}

// ---------------- z = mu + eps*exp(0.5 lv); accumulate KL ----------------
__global__ void z_kl(const float* __restrict__ A2, const float* __restrict__ bmu,
                     const float* __restrict__ blv, const float* __restrict__ eps,
                     float* __restrict__ Z) {
    __shared__ float red[256];
    int idx = blockIdx.x * blockDim.x + threadIdx.x;
    float t = 0.f;
    if (idx < NN * 64) {
        int n = idx >> 6, j = idx & 63;
        float mu = A2[(size_t)n * 128 + j] + bmu[j];
        float lv = A2[(size_t)n * 128 + 64 + j] + blv[j];
        Z[idx] = mu + eps[idx] * expf(0.5f * lv);
        t = 1.f + lv - mu * mu - expf(lv);
    }
    red[threadIdx.x] = t;
    __syncthreads();
    for (int o = 128; o; o >>= 1) {
        if (threadIdx.x < o) red[threadIdx.x] += red[threadIdx.x + o];
        __syncthreads();
    }
    if (threadIdx.x == 0) atomicAdd(&g_acc[0], (double)red[0]);
}

// ---------------- decoder degree / dis ----------------
__global__ void deg_count(const int* __restrict__ pd) {
    int e = blockIdx.x * blockDim.x + threadIdx.x;
    if (e < EP) atomicAdd(&g_deg[pd[e]], 1);
}
__global__ void dis_kernel() {
    int n = blockIdx.x * blockDim.x + threadIdx.x;
    if (n < NN) g_dis[n] = rsqrtf((float)g_deg[n] + 1.0f);
}

// ---------------- normalized scatter ----------------
__global__ void scatter_norm(const float* __restrict__ M, const int* __restrict__ ps,
                             const int* __restrict__ pd, float* __restrict__ A) {
    int idx = blockIdx.x * blockDim.x + threadIdx.x;
    int e = idx >> 4, c = idx & 15;
    if (e >= EP + NN) return;
    int s, d; float coef;
    if (e < EP) { s = ps[e]; d = pd[e]; coef = g_dis[s] * g_dis[d]; }
    else        { s = d = e - EP; float x = g_dis[s]; coef = x * x; }
    float4 v = *(const float4*)&M[(size_t)s * 64 + c * 4];
    red4(&A[(size_t)d * 64 + c * 4], v.x * coef, v.y * coef, v.z * coef, v.w * coef);
}

__global__ void bias_relu(const float* __restrict__ A, const float* __restrict__ b,
                          float* __restrict__ H) {
    int idx = blockIdx.x * blockDim.x + threadIdx.x;
    if (idx < NN * 64) H[idx] = fmaxf(A[idx] + b[idx & 63], 0.f);
}

// ---------------- edge MLP + BCE via tf32 tensor cores ----------------
#define DS_S 132
#define WS_S 72
__global__ void edge_mlp_tc(const float* __restrict__ h, const float* __restrict__ P,
                            const int* __restrict__ pos, const int* __restrict__ neg,
                            const float* __restrict__ Wa, const float* __restrict__ ba,
                            const float* __restrict__ Wb, const float* __restrict__ bb,
                            const float* __restrict__ tau) {
    extern __shared__ float sm[];
    float* Ws   = sm;                    // [128][WS_S]
    float* Ds   = Ws + 128 * WS_S;       // [64][DS_S]
    float* sba  = Ds + 64 * DS_S;        // 64
    float* sWb  = sba + 64;              // 64
    float* slog = sWb + 64;              // 64
    float* red  = slog + 64;             // 256
    int*   su   = (int*)(red + 256);     // 64
    int*   sv   = su + 64;               // 64

    int t = threadIdx.x;
    int w = t >> 5, lane = t & 31;
    int g = lane >> 2, t4 = lane & 3;
    int r0 = (w & 3) * 16;
    int n0 = (w >> 2) * 32;

    for (int i = t; i < 128 * 64; i += 256) {
        int k = i >> 6, j = i & 63;
        Ws[k * WS_S + j] = __uint_as_float(f2tf32(Wa[(size_t)(128 + k) * 64 + j]));
    }
    if (t < 64) { sba[t] = ba[t]; sWb[t] = Wb[t]; }
    float tau_c = fmaxf(tau[0], 1e-4f);
    float bb0 = bb[0];
    float loc = 0.f;

    const int NTILES = ET / 64;
    for (int tb = blockIdx.x; tb < NTILES; tb += gridDim.x) {
        int e0 = tb * 64;
        __syncthreads();
        if (t < 64) {
            int e = e0 + t;
            if (e < EP) { su[t] = pos[e]; sv[t] = pos[EP + e]; }
            else        { su[t] = neg[e - EP]; sv[t] = neg[EN + (e - EP)]; }
            slog[t] = 0.f;
        }
        __syncthreads();

        {
            int ee = t >> 2, part = t & 3;
            int u = su[ee], v = sv[ee];
            const float4* hu4 = (const float4*)&h[(size_t)u * 64];
            const float4* hv4 = (const float4*)&h[(size_t)v * 64];
#pragma unroll
            for (int q = 0; q < 4; q++) {
                float4 a = hu4[part * 4 + q];
                float4 b = hv4[part * 4 + q];
                int kk = part * 16 + q * 4;
                float4 dv, pv;
                dv.x = __uint_as_float(f2tf32(fabsf(a.x - b.x)));
                dv.y = __uint_as_float(f2tf32(fabsf(a.y - b.y)));
                dv.z = __uint_as_float(f2tf32(fabsf(a.z - b.z)));
                dv.w = __uint_as_float(f2tf32(fabsf(a.w - b.w)));
                pv.x = __uint_as_float(f2tf32(a.x * b.x));
                pv.y = __uint_as_float(f2tf32(a.y * b.y));
                pv.z = __uint_as_float(f2tf32(a.z * b.z));
                pv.w = __uint_as_float(f2tf32(a.w * b.w));
                *(float4*)&Ds[ee * DS_S + kk] = dv;
                *(float4*)&Ds[ee * DS_S + 64 + kk] = pv;
            }
        }

        float acc[4][4];
        {
            int uA = su[r0 + g],     vA = sv[r0 + g];
            int uB = su[r0 + g + 8], vB = sv[r0 + g + 8];
#pragma unroll
            for (int s = 0; s < 4; s++) {
                int j0 = n0 + s * 8 + t4 * 2;
                float2 p1 = *(const float2*)&P[(size_t)uA * 128 + j0];
                float2 p2 = *(const float2*)&P[(size_t)vA * 128 + 64 + j0];
                acc[s][0] = p1.x + p2.x; acc[s][1] = p1.y + p2.y;
                float2 q1 = *(const float2*)&P[(size_t)uB * 128 + j0];
                float2 q2 = *(const float2*)&P[(size_t)vB * 128 + 64 + j0];
                acc[s][2] = q1.x + q2.x; acc[s][3] = q1.y + q2.y;
            }
        }
        __syncthreads();

#pragma unroll 4
        for (int ks = 0; ks < 16; ks++) {
            int k0 = ks * 8;
            unsigned a0 = __float_as_uint(Ds[(r0 + g) * DS_S + k0 + t4]);
            unsigned a1 = __float_as_uint(Ds[(r0 + g + 8) * DS_S + k0 + t4]);
            unsigned a2 = __float_as_uint(Ds[(r0 + g) * DS_S + k0 + t4 + 4]);
            unsigned a3 = __float_as_uint(Ds[(r0 + g + 8) * DS_S + k0 + t4 + 4]);
#pragma unroll
            for (int s = 0; s < 4; s++) {
                int n = n0 + s * 8 + g;
                unsigned b0 = __float_as_uint(Ws[(k0 + t4) * WS_S + n]);
                unsigned b1 = __float_as_uint(Ws[(k0 + t4 + 4) * WS_S + n]);
                mma_tf32(acc[s][0], acc[s][1], acc[s][2], acc[s][3],
                         a0, a1, a2, a3, b0, b1);
            }
        }

        {
            float p_lo = 0.f, p_hi = 0.f;
#pragma unroll
            for (int s = 0; s < 4; s++) {
                int j0 = n0 + s * 8 + t4 * 2;
                p_lo += fmaxf(acc[s][0] + sba[j0], 0.f) * sWb[j0]
                      + fmaxf(acc[s][1] + sba[j0 + 1], 0.f) * sWb[j0 + 1];
                p_hi += fmaxf(acc[s][2] + sba[j0], 0.f) * sWb[j0]
                      + fmaxf(acc[s][3] + sba[j0 + 1], 0.f) * sWb[j0 + 1];
            }
            p_lo += __shfl_down_sync(0xffffffffu, p_lo, 2, 4);
            p_lo += __shfl_down_sync(0xffffffffu, p_lo, 1, 4);
            p_hi += __shfl_down_sync(0xffffffffu, p_hi, 2, 4);
            p_hi += __shfl_down_sync(0xffffffffu, p_hi, 1, 4);
            if (t4 == 0) {
                atomicAdd(&slog[r0 + g], p_lo);
                atomicAdd(&slog[r0 + g + 8], p_hi);
            }
        }
        __syncthreads();

        if (t < 64) {
            float l = (slog[t] + bb0) / tau_c;
            int ge = e0 + t;
            loc += (ge < EP) ? (-5.0f * logsig(l)) : (-logsig(-l));
        }
    }
    __syncthreads();
    red[t] = loc;
    __syncthreads();
    for (int o = 128; o; o >>= 1) {
        if (t < o) red[t] += red[t + o];
        __syncthreads();
    }
    if (t == 0) atomicAdd(&g_acc[1], (double)red[0]);
}

// ---------------- finalize ----------------
__global__ void finalize_k(float* out, int out_size) {
    double kl = -0.5 * g_acc[0] / (double)(NN * 64);
    double recon = g_acc[1] / (double)ET;
    if (out_size >= 3) {
        out[0] = (float)(recon + kl);
        out[1] = (float)recon;
        out[2] = (float)kl;
    } else {
        out[0] = (float)(recon + kl);
    }
}

// ---------------- launch ----------------
extern "C" void kernel_launch(void* const* d_in, const int* in_sizes, int n_in,
                              void* d_out, int out_size) {
    const float* x    = (const float*)d_in[0];
    const float* eps  = (const float*)d_in[1];
    const int* ei     = (const int*)d_in[2];
    const int* pos    = (const int*)d_in[3];
    const int* neg    = (const int*)d_in[4];
    const float* W1   = (const float*)d_in[5];
    const float* b1   = (const float*)d_in[6];
    const float* g1   = (const float*)d_in[7];
    const float* bt1  = (const float*)d_in[8];
    const float* Wmu  = (const float*)d_in[9];
    const float* bmu  = (const float*)d_in[10];
    const float* Wlv  = (const float*)d_in[11];
    const float* blv  = (const float*)d_in[12];
    const float* Wd1  = (const float*)d_in[13];
    const float* bd1  = (const float*)d_in[14];
    const float* Wd2  = (const float*)d_in[15];
    const float* bd2  = (const float*)d_in[16];
    const float* Wa   = (const float*)d_in[17];
    const float* ba   = (const float*)d_in[18];
    const float* Wb   = (const float*)d_in[19];
    const float* bb   = (const float*)d_in[20];
    const float* tau  = (const float*)d_in[21];
    float* out = (float*)d_out;

    const int* src = ei;
    const int* dst = ei + E2;
    const int* ps  = pos;
    const int* pd  = pos + EP;

    float *M1, *A1, *H1, *M2, *A2, *Z, *M3, *A3a, *A3b, *HD1, *HD2, *Pm;
    cudaGetSymbolAddress((void**)&M1, g_M1);
    cudaGetSymbolAddress((void**)&A1, g_A1);
    cudaGetSymbolAddress((void**)&H1, g_H1);
    cudaGetSymbolAddress((void**)&M2, g_M2);
    cudaGetSymbolAddress((void**)&A2, g_A2);
    cudaGetSymbolAddress((void**)&Z,  g_Z);
    cudaGetSymbolAddress((void**)&M3, g_M3);
    cudaGetSymbolAddress((void**)&A3a, g_A3a);
    cudaGetSymbolAddress((void**)&A3b, g_A3b);
    cudaGetSymbolAddress((void**)&HD1, g_HD1);
    cudaGetSymbolAddress((void**)&HD2, g_HD2);
    cudaGetSymbolAddress((void**)&Pm, g_P);

    const int EDGE_SMEM = (128 * WS_S + 64 * DS_S + 64 * 3 + 256 + 128) * 4;
    cudaFuncSetAttribute(edge_mlp_tc, cudaFuncAttributeMaxDynamicSharedMemorySize, EDGE_SMEM);

    zero_all<<<2048, 256>>>();

    const int GM = (NN + 63) / 64;   // 313
    gemm_tf32<<<dim3(GM, 4), 256>>>(x, 256, W1, 256, M1, 256, NN, 256);

    scatter_add<<<(E2 * 32 + 255) / 256, 256>>>(M1, src, dst, A1, E2, 64);
    ln_relu<<<(NN * 32 + 255) / 256, 256>>>(A1, b1, g1, bt1, H1);

    gemm_tf32<<<dim3(GM, 1), 256>>>(H1, 256, Wmu, 64, M2,      128, NN, 256);
    gemm_tf32<<<dim3(GM, 1), 256>>>(H1, 256, Wlv, 64, M2 + 64, 128, NN, 256);
    scatter_add<<<(E2 * 32 + 255) / 256, 256>>>(M2, src, dst, A2, E2, 32);
    z_kl<<<(NN * 64 + 255) / 256, 256>>>(A2, bmu, blv, eps, Z);

    deg_count<<<(EP + 255) / 256, 256>>>(pd);
    dis_kernel<<<(NN + 255) / 256, 256>>>();

    gemm_tf32<<<dim3(GM, 1), 256>>>(Z, 64, Wd1, 64, M3, 64, NN, 64);
    scatter_norm<<<((EP + NN) * 16 + 255) / 256, 256>>>(M3, ps, pd, A3a);
    bias_relu<<<(NN * 64 + 255) / 256, 256>>>(A3a, bd1, HD1);

    gemm_tf32<<<dim3(GM, 1), 256>>>(HD1, 64, Wd2, 64, M3, 64, NN, 64);
    scatter_norm<<<((EP + NN) * 16 + 255) / 256, 256>>>(M3, ps, pd, A3b);
    bias_relu<<<(NN * 64 + 255) / 256, 256>>>(A3b, bd2, HD2);

    gemm_tf32<<<dim3(GM, 1), 256>>>(HD2, 64, Wa,           64, Pm,      128, NN, 64);
    gemm_tf32<<<dim3(GM, 1), 256>>>(HD2, 64, Wa + 64 * 64, 64, Pm + 64, 128, NN, 64);

    edge_mlp_tc<<<444, 256, EDGE_SMEM>>>(HD2, Pm, pos, neg, Wa, ba, Wb, bb, tau);

    finalize_k<<<1, 1>>>(out, out_size);
}

// round 6
// speedup vs baseline: 1.8137x; 1.1749x over previous
#include <cuda_runtime.h>
#include <cuda_bf16.h>
#include <math.h>

// ---------------- problem constants ----------------
#define NN      20000
#define EP      120000      // positive edges
#define EN      600000      // negative edges (NEG*E)
#define ET      720000      // total scored edges
#define E2      240000      // directed encoder edges (2E)
#define LN_EPS  1e-5f

// ---------------- scratch ----------------
__device__ float  g_M1[NN * 256];   // x@W1
__device__ float  g_A1[NN * 256];   // scatter accum layer1
__device__ float  g_H1[NN * 256];   // relu(LN(...))
__device__ float  g_M2[NN * 128];   // h1@[Wmu|Wlv]
__device__ float  g_A2[NN * 128];   // scatter accum mu|lv
__device__ float  g_Z [NN * 64];    // latent
__device__ float  g_M3[NN * 64];    // gemm scratch decoder
__device__ float  g_A3a[NN * 64];   // decoder accum pass1
__device__ float  g_A3b[NN * 64];   // decoder accum pass2
__device__ float  g_HD1[NN * 64];   // decoder hidden 1
__device__ float  g_HD2[NN * 64];   // decoder hidden 2 (= h)
__device__ float  g_P [NN * 128];   // [h@Wa1 | h@Wa2]
__device__ int    g_deg[NN];
__device__ float  g_dis[NN];
__device__ double g_acc[2];         // [0]=kl sum, [1]=recon sum

// ---------------- helpers ----------------
__device__ __forceinline__ void red4(float* p, float x, float y, float z, float w) {
    asm volatile("red.global.add.v4.f32 [%0], {%1,%2,%3,%4};"
                 :: "l"(p), "f"(x), "f"(y), "f"(z), "f"(w) : "memory");
}
__device__ __forceinline__ float logsig(float x) {
    return fminf(x, 0.0f) - log1pf(expf(-fabsf(x)));
}
__device__ __forceinline__ unsigned f2tf32(float x) {
    unsigned r;
    asm("cvt.rna.tf32.f32 %0, %1;" : "=r"(r) : "f"(x));
    return r;
}
__device__ __forceinline__ void mma_tf32(float& d0, float& d1, float& d2, float& d3,
                                         unsigned a0, unsigned a1, unsigned a2, unsigned a3,
                                         unsigned b0, unsigned b1) {
    asm volatile("mma.sync.aligned.m16n8k8.row.col.f32.tf32.tf32.f32 "
                 "{%0,%1,%2,%3}, {%4,%5,%6,%7}, {%8,%9}, {%0,%1,%2,%3};"
                 : "+f"(d0), "+f"(d1), "+f"(d2), "+f"(d3)
                 : "r"(a0), "r"(a1), "r"(a2), "r"(a3), "r"(b0), "r"(b1));
}
__device__ __forceinline__ void mma_bf16(float& d0, float& d1, float& d2, float& d3,
                                         unsigned a0, unsigned a1, unsigned a2, unsigned a3,
                                         unsigned b0, unsigned b1) {
    asm volatile("mma.sync.aligned.m16n8k16.row.col.f32.bf16.bf16.f32 "
                 "{%0,%1,%2,%3}, {%4,%5,%6,%7}, {%8,%9}, {%0,%1,%2,%3};"
                 : "+f"(d0), "+f"(d1), "+f"(d2), "+f"(d3)
                 : "r"(a0), "r"(a1), "r"(a2), "r"(a3), "r"(b0), "r"(b1));
}

// ---------------- zero scratch ----------------
__global__ void zero_all() {
    size_t i = (size_t)blockIdx.x * blockDim.x + threadIdx.x;
    size_t st = (size_t)gridDim.x * blockDim.x;
    for (size_t k = i; k < (size_t)NN * 256; k += st) g_A1[k] = 0.f;
    for (size_t k = i; k < (size_t)NN * 128; k += st) g_A2[k] = 0.f;
    for (size_t k = i; k < (size_t)NN * 64;  k += st) { g_A3a[k] = 0.f; g_A3b[k] = 0.f; }
    for (size_t k = i; k < NN; k += st) g_deg[k] = 0;
    if (i == 0) { g_acc[0] = 0.0; g_acc[1] = 0.0; }
}

// ---------------- tf32 tensor-core GEMM: C[M,N] = A[M,K] @ W[K,N] -------------
#define AS_S 36
#define WSG_S 72
__device__ __forceinline__ void gemm_tf32_body(
        const float* __restrict__ A, int lda,
        const float* __restrict__ W, int ldw,
        float* __restrict__ C, int ldc,
        int M, int Kin, int m0, int nb) {
    __shared__ float As[64 * AS_S];
    __shared__ float Ws[32 * WSG_S];
    int t = threadIdx.x;
    int w = t >> 5, lane = t & 31;
    int g = lane >> 2, t4 = lane & 3;
    int r0 = (w & 3) * 16;
    int n0 = (w >> 2) * 32;
    int ar = t >> 2, ak = (t & 3) * 8;
    int wk = t >> 3, wn = (t & 7) * 8;

    float acc[4][4];
#pragma unroll
    for (int s = 0; s < 4; s++)
#pragma unroll
        for (int j = 0; j < 4; j++) acc[s][j] = 0.f;

    for (int k0 = 0; k0 < Kin; k0 += 32) {
        {
            int gm = m0 + ar;
            float4 v0 = make_float4(0.f,0.f,0.f,0.f), v1 = v0;
            if (gm < M) {
                const float* ap = &A[(size_t)gm * lda + k0 + ak];
                v0 = *(const float4*)ap;
                v1 = *(const float4*)(ap + 4);
            }
            float* d = &As[ar * AS_S + ak];
            d[0] = __uint_as_float(f2tf32(v0.x)); d[1] = __uint_as_float(f2tf32(v0.y));
            d[2] = __uint_as_float(f2tf32(v0.z)); d[3] = __uint_as_float(f2tf32(v0.w));
            d[4] = __uint_as_float(f2tf32(v1.x)); d[5] = __uint_as_float(f2tf32(v1.y));
            d[6] = __uint_as_float(f2tf32(v1.z)); d[7] = __uint_as_float(f2tf32(v1.w));
        }
        {
            const float* wp = &W[(size_t)(k0 + wk) * ldw + nb + wn];
            float4 v0 = *(const float4*)wp;
            float4 v1 = *(const float4*)(wp + 4);
            float* d = &Ws[wk * WSG_S + wn];
            d[0] = __uint_as_float(f2tf32(v0.x)); d[1] = __uint_as_float(f2tf32(v0.y));
            d[2] = __uint_as_float(f2tf32(v0.z)); d[3] = __uint_as_float(f2tf32(v0.w));
            d[4] = __uint_as_float(f2tf32(v1.x)); d[5] = __uint_as_float(f2tf32(v1.y));
            d[6] = __uint_as_float(f2tf32(v1.z)); d[7] = __uint_as_float(f2tf32(v1.w));
        }
        __syncthreads();
#pragma unroll
        for (int ks = 0; ks < 4; ks++) {
            int kk = ks * 8;
            unsigned a0 = __float_as_uint(As[(r0 + g) * AS_S + kk + t4]);
            unsigned a1 = __float_as_uint(As[(r0 + g + 8) * AS_S + kk + t4]);
            unsigned a2 = __float_as_uint(As[(r0 + g) * AS_S + kk + t4 + 4]);
            unsigned a3 = __float_as_uint(As[(r0 + g + 8) * AS_S + kk + t4 + 4]);
#pragma unroll
            for (int s = 0; s < 4; s++) {
                int n = n0 + s * 8 + g;
                unsigned b0 = __float_as_uint(Ws[(kk + t4) * WSG_S + n]);
                unsigned b1 = __float_as_uint(Ws[(kk + t4 + 4) * WSG_S + n]);
                mma_tf32(acc[s][0], acc[s][1], acc[s][2], acc[s][3],
                         a0, a1, a2, a3, b0, b1);
            }
        }
        __syncthreads();
    }
    int gmA = m0 + r0 + g, gmB = gmA + 8;
#pragma unroll
    for (int s = 0; s < 4; s++) {
        int cn = n0 + s * 8 + t4 * 2;
        if (gmA < M) *(float2*)&C[(size_t)gmA * ldc + cn] = make_float2(acc[s][0], acc[s][1]);
        if (gmB < M) *(float2*)&C[(size_t)gmB * ldc + cn] = make_float2(acc[s][2], acc[s][3]);
    }
}

__global__ void gemm_tf32(const float* __restrict__ A, int lda,
                          const float* __restrict__ W, int ldw,
                          float* __restrict__ C, int ldc,
                          int M, int Kin) {
    // C block column handled via pointer: nb within W, C offset
    gemm_tf32_body(A, lda, W, ldw, C + blockIdx.y * 64, ldc, M, Kin,
                   blockIdx.x * 64, blockIdx.y * 64);
}

// dual-weight variant: blockIdx.y selects (W0 -> C cols [0,64)) or (W1 -> C cols [64,128))
__global__ void gemm_tf32_dual(const float* __restrict__ A, int lda,
                               const float* __restrict__ W0, const float* __restrict__ W1,
                               int ldw, float* __restrict__ C, int ldc,
                               int M, int Kin) {
    const float* W = blockIdx.y ? W1 : W0;
    gemm_tf32_body(A, lda, W, ldw, C + blockIdx.y * 64, ldc, M, Kin,
                   blockIdx.x * 64, 0);
}

// ---------------- scatter-add ----------------
__global__ void scatter_add(const float* __restrict__ M, const int* __restrict__ src,
                            const int* __restrict__ dst, float* __restrict__ A,
                            int nE, int F4) {
    int gt = blockIdx.x * blockDim.x + threadIdx.x;
    int e = gt >> 5, lane = gt & 31;
    if (e >= nE) return;
    int s = src[e], d = dst[e];
    const float4* Mr = (const float4*)&M[(size_t)s * (F4 * 4)];
    float* Ar = &A[(size_t)d * (F4 * 4)];
    for (int c = lane; c < F4; c += 32) {
        float4 v = Mr[c];
        red4(Ar + c * 4, v.x, v.y, v.z, v.w);
    }
}

// ---------------- LayerNorm + ReLU ----------------
__global__ void ln_relu(const float* __restrict__ A, const float* __restrict__ b,
                        const float* __restrict__ g, const float* __restrict__ bt,
                        float* __restrict__ H) {
    int w = (blockIdx.x * blockDim.x + threadIdx.x) >> 5;
    int lane = threadIdx.x & 31;
    if (w >= NN) return;
    float v[8];
    float s = 0.f;
#pragma unroll
    for (int i = 0; i < 8; i++) {
        int j = i * 32 + lane;
        v[i] = A[(size_t)w * 256 + j] + b[j];
        s += v[i];
    }
#pragma unroll
    for (int o = 16; o; o >>= 1) s += __shfl_xor_sync(0xffffffffu, s, o);
    float mu = s * (1.f / 256.f);
    float s2 = 0.f;
#pragma unroll
    for (int i = 0; i < 8; i++) { float d = v[i] - mu; s2 += d * d; }
#pragma unroll
    for (int o = 16; o; o >>= 1) s2 += __shfl_xor_sync(0xffffffffu, s2, o);
    float inv = rsqrtf(s2 * (1.f / 256.f) + LN_EPS);
#pragma unroll
    for (int i = 0; i < 8; i++) {
        int j = i * 32 + lane;
        H[(size_t)w * 256 + j] = fmaxf((v[i] - mu) * inv * g[j] + bt[j], 0.f);
    }
}

// ---------------- z = mu + eps*exp(0.5 lv); accumulate KL ----------------
__global__ void z_kl(const float* __restrict__ A2, const float* __restrict__ bmu,
                     const float* __restrict__ blv, const float* __restrict__ eps,
                     float* __restrict__ Z) {
    __shared__ float red[256];
    int idx = blockIdx.x * blockDim.x + threadIdx.x;
    float t = 0.f;
    if (idx < NN * 64) {
        int n = idx >> 6, j = idx & 63;
        float mu = A2[(size_t)n * 128 + j] + bmu[j];
        float lv = A2[(size_t)n * 128 + 64 + j] + blv[j];
        Z[idx] = mu + eps[idx] * expf(0.5f * lv);
        t = 1.f + lv - mu * mu - expf(lv);
    }
    red[threadIdx.x] = t;
    __syncthreads();
    for (int o = 128; o; o >>= 1) {
        if (threadIdx.x < o) red[threadIdx.x] += red[threadIdx.x + o];
        __syncthreads();
    }
    if (threadIdx.x == 0) atomicAdd(&g_acc[0], (double)red[0]);
}

// ---------------- decoder degree / dis ----------------
__global__ void deg_count(const int* __restrict__ pd) {
    int e = blockIdx.x * blockDim.x + threadIdx.x;
    if (e < EP) atomicAdd(&g_deg[pd[e]], 1);
}
__global__ void dis_kernel() {
    int n = blockIdx.x * blockDim.x + threadIdx.x;
    if (n < NN) g_dis[n] = rsqrtf((float)g_deg[n] + 1.0f);
}

// ---------------- normalized scatter ----------------
__global__ void scatter_norm(const float* __restrict__ M, const int* __restrict__ ps,
                             const int* __restrict__ pd, float* __restrict__ A) {
    int idx = blockIdx.x * blockDim.x + threadIdx.x;
    int e = idx >> 4, c = idx & 15;
    if (e >= EP + NN) return;
    int s, d; float coef;
    if (e < EP) { s = ps[e]; d = pd[e]; coef = g_dis[s] * g_dis[d]; }
    else        { s = d = e - EP; float x = g_dis[s]; coef = x * x; }
    float4 v = *(const float4*)&M[(size_t)s * 64 + c * 4];
    red4(&A[(size_t)d * 64 + c * 4], v.x * coef, v.y * coef, v.z * coef, v.w * coef);
}

__global__ void bias_relu(const float* __restrict__ A, const float* __restrict__ b,
                          float* __restrict__ H) {
    int idx = blockIdx.x * blockDim.x + threadIdx.x;
    if (idx < NN * 64) H[idx] = fmaxf(A[idx] + b[idx & 63], 0.f);
}

// ---------------- edge MLP + BCE via bf16 tensor cores (m16n8k16) ----------------
// 64 edges x 64 hidden tile, K=128 nonlinear features ([|hu-hv|; hu*hv]) in bf16;
// linear part P1[u]+P2[v] seeded fp32. Ds2 [edge][k], Ws2 [n][k] (B k-pairs contiguous).
#define DS2_S 136
#define WS2_S 136
__global__ void edge_mlp_bf16(const float* __restrict__ h, const float* __restrict__ P,
                              const int* __restrict__ pos, const int* __restrict__ neg,
                              const float* __restrict__ Wa, const float* __restrict__ ba,
                              const float* __restrict__ Wb, const float* __restrict__ bb,
                              const float* __restrict__ tau) {
    extern __shared__ char smraw[];
    float* red  = (float*)smraw;                 // 256
    float* sba  = red + 256;                     // 64
    float* sWb  = sba + 64;                      // 64
    float* slog = sWb + 64;                      // 64
    int*   su   = (int*)(slog + 64);             // 64
    int*   sv   = su + 64;                       // 64
    __nv_bfloat16* Ws2 = (__nv_bfloat16*)(sv + 64);       // [64 n][WS2_S k]
    __nv_bfloat16* Ds2 = Ws2 + 64 * WS2_S;                // [64 e][DS2_S k]

    int t = threadIdx.x;
    int w = t >> 5, lane = t & 31;
    int g = lane >> 2, t4 = lane & 3;
    int r0 = (w & 3) * 16;
    int n0 = (w >> 2) * 32;

    // stage weights transposed: Ws2[n][k] = bf16(Wa[(128+k)*64 + n])
    for (int i = t; i < 64 * 128; i += 256) {
        int n = i & 63, k = i >> 6;
        Ws2[n * WS2_S + k] = __float2bfloat16(Wa[(size_t)(128 + k) * 64 + n]);
    }
    if (t < 64) { sba[t] = ba[t]; sWb[t] = Wb[t]; }
    float tau_c = fmaxf(tau[0], 1e-4f);
    float bb0 = bb[0];
    float loc = 0.f;

    const int NTILES = ET / 64;
    for (int tb = blockIdx.x; tb < NTILES; tb += gridDim.x) {
        int e0 = tb * 64;
        __syncthreads();
        if (t < 64) {
            int e = e0 + t;
            if (e < EP) { su[t] = pos[e]; sv[t] = pos[EP + e]; }
            else        { su[t] = neg[e - EP]; sv[t] = neg[EN + (e - EP)]; }
            slog[t] = 0.f;
        }
        __syncthreads();

        // build bf16 feature tile
        {
            int ee = t >> 2, part = t & 3;
            int u = su[ee], v = sv[ee];
            const float4* hu4 = (const float4*)&h[(size_t)u * 64];
            const float4* hv4 = (const float4*)&h[(size_t)v * 64];
#pragma unroll
            for (int q = 0; q < 4; q++) {
                float4 a = hu4[part * 4 + q];
                float4 b = hv4[part * 4 + q];
                int kk = part * 16 + q * 4;
                __nv_bfloat162* dd = (__nv_bfloat162*)&Ds2[ee * DS2_S + kk];
                dd[0] = __float22bfloat162_rn(make_float2(fabsf(a.x - b.x), fabsf(a.y - b.y)));
                dd[1] = __float22bfloat162_rn(make_float2(fabsf(a.z - b.z), fabsf(a.w - b.w)));
                __nv_bfloat162* pp = (__nv_bfloat162*)&Ds2[ee * DS2_S + 64 + kk];
                pp[0] = __float22bfloat162_rn(make_float2(a.x * b.x, a.y * b.y));
                pp[1] = __float22bfloat162_rn(make_float2(a.z * b.z, a.w * b.w));
            }
        }

        // seed acc with P1[u] + P2[v]
        float acc[4][4];
        {
            int uA = su[r0 + g],     vA = sv[r0 + g];
            int uB = su[r0 + g + 8], vB = sv[r0 + g + 8];
#pragma unroll
            for (int s = 0; s < 4; s++) {
                int j0 = n0 + s * 8 + t4 * 2;
                float2 p1 = *(const float2*)&P[(size_t)uA * 128 + j0];
                float2 p2 = *(const float2*)&P[(size_t)vA * 128 + 64 + j0];
                acc[s][0] = p1.x + p2.x; acc[s][1] = p1.y + p2.y;
                float2 q1 = *(const float2*)&P[(size_t)uB * 128 + j0];
                float2 q2 = *(const float2*)&P[(size_t)vB * 128 + 64 + j0];
                acc[s][2] = q1.x + q2.x; acc[s][3] = q1.y + q2.y;
            }
        }
        __syncthreads();

        // K loop: 8 steps of k=16 (bf16)
#pragma unroll
        for (int ks = 0; ks < 8; ks++) {
            int k0 = ks * 16;
            unsigned a0 = *(const unsigned*)&Ds2[(r0 + g) * DS2_S + k0 + t4 * 2];
            unsigned a1 = *(const unsigned*)&Ds2[(r0 + g + 8) * DS2_S + k0 + t4 * 2];
            unsigned a2 = *(const unsigned*)&Ds2[(r0 + g) * DS2_S + k0 + t4 * 2 + 8];
            unsigned a3 = *(const unsigned*)&Ds2[(r0 + g + 8) * DS2_S + k0 + t4 * 2 + 8];
#pragma unroll
            for (int s = 0; s < 4; s++) {
                int n = n0 + s * 8 + g;
                unsigned b0 = *(const unsigned*)&Ws2[n * WS2_S + k0 + t4 * 2];
                unsigned b1 = *(const unsigned*)&Ws2[n * WS2_S + k0 + t4 * 2 + 8];
                mma_bf16(acc[s][0], acc[s][1], acc[s][2], acc[s][3],
                         a0, a1, a2, a3, b0, b1);
            }
        }

        // epilogue: relu + Wb dot, 4-lane reduce, smem atomics
        {
            float p_lo = 0.f, p_hi = 0.f;
#pragma unroll
            for (int s = 0; s < 4; s++) {
                int j0 = n0 + s * 8 + t4 * 2;
                p_lo += fmaxf(acc[s][0] + sba[j0], 0.f) * sWb[j0]
                      + fmaxf(acc[s][1] + sba[j0 + 1], 0.f) * sWb[j0 + 1];
                p_hi += fmaxf(acc[s][2] + sba[j0], 0.f) * sWb[j0]
                      + fmaxf(acc[s][3] + sba[j0 + 1], 0.f) * sWb[j0 + 1];
            }
            p_lo += __shfl_down_sync(0xffffffffu, p_lo, 2, 4);
            p_lo += __shfl_down_sync(0xffffffffu, p_lo, 1, 4);
            p_hi += __shfl_down_sync(0xffffffffu, p_hi, 2, 4);
            p_hi += __shfl_down_sync(0xffffffffu, p_hi, 1, 4);
            if (t4 == 0) {
                atomicAdd(&slog[r0 + g], p_lo);
                atomicAdd(&slog[r0 + g + 8], p_hi);
            }
        }
        __syncthreads();

        if (t < 64) {
            float l = (slog[t] + bb0) / tau_c;
            int ge = e0 + t;
            loc += (ge < EP) ? (-5.0f * logsig(l)) : (-logsig(-l));
        }
    }
    __syncthreads();
    red[t] = loc;
    __syncthreads();
    for (int o = 128; o; o >>= 1) {
        if (t < o) red[t] += red[t + o];
        __syncthreads();
    }
    if (t == 0) atomicAdd(&g_acc[1], (double)red[0]);
}

// ---------------- finalize ----------------
__global__ void finalize_k(float* out, int out_size) {
    double kl = -0.5 * g_acc[0] / (double)(NN * 64);
    double recon = g_acc[1] / (double)ET;
    if (out_size >= 3) {
        out[0] = (float)(recon + kl);
        out[1] = (float)recon;
        out[2] = (float)kl;
    } else {
        out[0] = (float)(recon + kl);
    }
}

// ---------------- launch ----------------
extern "C" void kernel_launch(void* const* d_in, const int* in_sizes, int n_in,
                              void* d_out, int out_size) {
    const float* x    = (const float*)d_in[0];
    const float* eps  = (const float*)d_in[1];
    const int* ei     = (const int*)d_in[2];
    const int* pos    = (const int*)d_in[3];
    const int* neg    = (const int*)d_in[4];
    const float* W1   = (const float*)d_in[5];
    const float* b1   = (const float*)d_in[6];
    const float* g1   = (const float*)d_in[7];
    const float* bt1  = (const float*)d_in[8];
    const float* Wmu  = (const float*)d_in[9];
    const float* bmu  = (const float*)d_in[10];
    const float* Wlv  = (const float*)d_in[11];
    const float* blv  = (const float*)d_in[12];
    const float* Wd1  = (const float*)d_in[13];
    const float* bd1  = (const float*)d_in[14];
    const float* Wd2  = (const float*)d_in[15];
    const float* bd2  = (const float*)d_in[16];
    const float* Wa   = (const float*)d_in[17];
    const float* ba   = (const float*)d_in[18];
    const float* Wb   = (const float*)d_in[19];
    const float* bb   = (const float*)d_in[20];
    const float* tau  = (const float*)d_in[21];
    float* out = (float*)d_out;

    const int* src = ei;
    const int* dst = ei + E2;
    const int* ps  = pos;
    const int* pd  = pos + EP;

    float *M1, *A1, *H1, *M2, *A2, *Z, *M3, *A3a, *A3b, *HD1, *HD2, *Pm;
    cudaGetSymbolAddress((void**)&M1, g_M1);
    cudaGetSymbolAddress((void**)&A1, g_A1);
    cudaGetSymbolAddress((void**)&H1, g_H1);
    cudaGetSymbolAddress((void**)&M2, g_M2);
    cudaGetSymbolAddress((void**)&A2, g_A2);
    cudaGetSymbolAddress((void**)&Z,  g_Z);
    cudaGetSymbolAddress((void**)&M3, g_M3);
    cudaGetSymbolAddress((void**)&A3a, g_A3a);
    cudaGetSymbolAddress((void**)&A3b, g_A3b);
    cudaGetSymbolAddress((void**)&HD1, g_HD1);
    cudaGetSymbolAddress((void**)&HD2, g_HD2);
    cudaGetSymbolAddress((void**)&Pm, g_P);

    const int EDGE_SMEM = (256 + 64 * 3) * 4 + 128 * 4 + (64 * WS2_S + 64 * DS2_S) * 2; // ~37 KB
    cudaFuncSetAttribute(edge_mlp_bf16, cudaFuncAttributeMaxDynamicSharedMemorySize, EDGE_SMEM);

    zero_all<<<2048, 256>>>();

    const int GM = (NN + 63) / 64;   // 313
    gemm_tf32<<<dim3(GM, 4), 256>>>(x, 256, W1, 256, M1, 256, NN, 256);

    scatter_add<<<(E2 * 32 + 255) / 256, 256>>>(M1, src, dst, A1, E2, 64);
    ln_relu<<<(NN * 32 + 255) / 256, 256>>>(A1, b1, g1, bt1, H1);

    gemm_tf32_dual<<<dim3(GM, 2), 256>>>(H1, 256, Wmu, Wlv, 64, M2, 128, NN, 256);
    scatter_add<<<(E2 * 32 + 255) / 256, 256>>>(M2, src, dst, A2, E2, 32);
    z_kl<<<(NN * 64 + 255) / 256, 256>>>(A2, bmu, blv, eps, Z);

    deg_count<<<(EP + 255) / 256, 256>>>(pd);
    dis_kernel<<<(NN + 255) / 256, 256>>>();

    gemm_tf32<<<dim3(GM, 1), 256>>>(Z, 64, Wd1, 64, M3, 64, NN, 64);
    scatter_norm<<<((EP + NN) * 16 + 255) / 256, 256>>>(M3, ps, pd, A3a);
    bias_relu<<<(NN * 64 + 255) / 256, 256>>>(A3a, bd1, HD1);

    gemm_tf32<<<dim3(GM, 1), 256>>>(HD1, 64, Wd2, 64, M3, 64, NN, 64);
    scatter_norm<<<((EP + NN) * 16 + 255) / 256, 256>>>(M3, ps, pd, A3b);
    bias_relu<<<(NN * 64 + 255) / 256, 256>>>(A3b, bd2, HD2);

    gemm_tf32_dual<<<dim3(GM, 2), 256>>>(HD2, 64, Wa, Wa + 64 * 64, 64, Pm, 128, NN, 64);

    edge_mlp_bf16<<<592, 256, EDGE_SMEM>>>(HD2, Pm, pos, neg, Wa, ba, Wb, bb, tau);

    finalize_k<<<1, 1>>>(out, out_size);
}

// round 8
// speedup vs baseline: 1.9065x; 1.0512x over previous
#include <cuda_runtime.h>
#include <cuda_bf16.h>
#include <math.h>

// ---------------- problem constants ----------------
#define NN      20000
#define EP      120000
#define EN      600000
#define ET      720000
#define E2      240000
#define LN_EPS  1e-5f

// ---------------- scratch ----------------
__device__ float  g_M1[NN * 256];
__device__ float  g_A1[NN * 256];
__device__ float  g_H1[NN * 256];
__device__ float  g_M2[NN * 128];
__device__ float  g_A2[NN * 128];
__device__ float  g_Z [NN * 64];
__device__ float  g_M3[NN * 64];
__device__ float  g_A3a[NN * 64];
__device__ float  g_A3b[NN * 64];
__device__ __nv_bfloat16 g_Hbf[NN * 64];    // h in bf16 (edge gather)
__device__ __nv_bfloat16 g_Pbf[NN * 128];   // [h@Wa1 | h@Wa2] bf16
__device__ int    g_deg[NN];
__device__ float  g_dis[NN];
__device__ double g_acc[2];

// ---------------- helpers ----------------
__device__ __forceinline__ void red4(float* p, float x, float y, float z, float w) {
    asm volatile("red.global.add.v4.f32 [%0], {%1,%2,%3,%4};"
                 :: "l"(p), "f"(x), "f"(y), "f"(z), "f"(w) : "memory");
}
__device__ __forceinline__ float logsig(float x) {
    return fminf(x, 0.0f) - log1pf(expf(-fabsf(x)));
}
__device__ __forceinline__ unsigned f2tf32(float x) {
    unsigned r;
    asm("cvt.rna.tf32.f32 %0, %1;" : "=r"(r) : "f"(x));
    return r;
}
__device__ __forceinline__ void mma_tf32(float& d0, float& d1, float& d2, float& d3,
                                         unsigned a0, unsigned a1, unsigned a2, unsigned a3,
                                         unsigned b0, unsigned b1) {
    asm volatile("mma.sync.aligned.m16n8k8.row.col.f32.tf32.tf32.f32 "
                 "{%0,%1,%2,%3}, {%4,%5,%6,%7}, {%8,%9}, {%0,%1,%2,%3};"
                 : "+f"(d0), "+f"(d1), "+f"(d2), "+f"(d3)
                 : "r"(a0), "r"(a1), "r"(a2), "r"(a3), "r"(b0), "r"(b1));
}
__device__ __forceinline__ void mma_bf16(float& d0, float& d1, float& d2, float& d3,
                                         unsigned a0, unsigned a1, unsigned a2, unsigned a3,
                                         unsigned b0, unsigned b1) {
    asm volatile("mma.sync.aligned.m16n8k16.row.col.f32.bf16.bf16.f32 "
                 "{%0,%1,%2,%3}, {%4,%5,%6,%7}, {%8,%9}, {%0,%1,%2,%3};"
                 : "+f"(d0), "+f"(d1), "+f"(d2), "+f"(d3)
                 : "r"(a0), "r"(a1), "r"(a2), "r"(a3), "r"(b0), "r"(b1));
}

struct __align__(16) BF8 { __nv_bfloat162 p[8]; };   // 16 bf16 = 32 B

// ---------------- zero scratch ----------------
__global__ void zero_all() {
    size_t i = (size_t)blockIdx.x * blockDim.x + threadIdx.x;
    size_t st = (size_t)gridDim.x * blockDim.x;
    for (size_t k = i; k < (size_t)NN * 256; k += st) g_A1[k] = 0.f;
    for (size_t k = i; k < (size_t)NN * 128; k += st) g_A2[k] = 0.f;
    for (size_t k = i; k < (size_t)NN * 64;  k += st) { g_A3a[k] = 0.f; g_A3b[k] = 0.f; }
    for (size_t k = i; k < NN; k += st) g_deg[k] = 0;
    if (i == 0) { g_acc[0] = 0.0; g_acc[1] = 0.0; }
}

// ---------------- double-buffered tf32 GEMM ----------------
// C[M,N64] = act(A[M,K] (+abias, relu)) @ W[K, nb..nb+64]
// block 256 thr, tile 64x64, K-chunks of 32, 2-stage smem pipeline.
#define AS_S 36
#define WSG_S 72
__device__ __forceinline__ void gemm_db_body(
        const float* __restrict__ A, int lda,
        const float* __restrict__ W, int ldw,
        float* __restrict__ C, int ldc,
        __nv_bfloat16* __restrict__ Cb, int ldcb,
        int M, int Kin, int m0, int nb,
        const float* __restrict__ abias) {
    __shared__ float As[2][64 * AS_S];
    __shared__ float Ws[2][32 * WSG_S];
    int t = threadIdx.x;
    int w = t >> 5, lane = t & 31;
    int g = lane >> 2, t4 = lane & 3;
    int r0 = (w & 3) * 16, n0 = (w >> 2) * 32;
    int ar = t >> 2, ak = (t & 3) * 8;
    int wk = t >> 3, wn = (t & 7) * 8;
    int gm = m0 + ar;
    bool am = gm < M;

    float a_r[8], w_r[8];

#define LOAD_CHUNK(K0)                                                         \
    {                                                                          \
        if (am) {                                                              \
            const float* ap = &A[(size_t)gm * lda + (K0) + ak];                \
            float4 v0 = *(const float4*)ap;                                    \
            float4 v1 = *(const float4*)(ap + 4);                              \
            a_r[0] = v0.x; a_r[1] = v0.y; a_r[2] = v0.z; a_r[3] = v0.w;        \
            a_r[4] = v1.x; a_r[5] = v1.y; a_r[6] = v1.z; a_r[7] = v1.w;        \
        } else {                                                               \
            _Pragma("unroll") for (int i = 0; i < 8; i++) a_r[i] = 0.f;        \
        }                                                                      \
        if (abias) {                                                           \
            _Pragma("unroll") for (int i = 0; i < 8; i++)                      \
                a_r[i] = fmaxf(a_r[i] + abias[(K0) + ak + i], 0.f);            \
        }                                                                      \
        const float* wp = &W[(size_t)((K0) + wk) * ldw + nb + wn];             \
        float4 u0 = *(const float4*)wp;                                        \
        float4 u1 = *(const float4*)(wp + 4);                                  \
        w_r[0] = u0.x; w_r[1] = u0.y; w_r[2] = u0.z; w_r[3] = u0.w;            \
        w_r[4] = u1.x; w_r[5] = u1.y; w_r[6] = u1.z; w_r[7] = u1.w;            \
    }

#define STORE_CHUNK(B)                                                         \
    {                                                                          \
        float* d = &As[B][ar * AS_S + ak];                                     \
        _Pragma("unroll") for (int i = 0; i < 8; i++)                          \
            d[i] = __uint_as_float(f2tf32(a_r[i]));                            \
        float* e = &Ws[B][wk * WSG_S + wn];                                    \
        _Pragma("unroll") for (int i = 0; i < 8; i++)                          \
            e[i] = __uint_as_float(f2tf32(w_r[i]));                            \
    }

    float acc[4][4];
#pragma unroll
    for (int s = 0; s < 4; s++)
#pragma unroll
        for (int j = 0; j < 4; j++) acc[s][j] = 0.f;

    LOAD_CHUNK(0)
    STORE_CHUNK(0)
    __syncthreads();

    int NC = Kin >> 5;
    for (int c = 0; c < NC; c++) {
        if (c + 1 < NC) LOAD_CHUNK((c + 1) * 32)
        int b = c & 1;
#pragma unroll
        for (int ks = 0; ks < 4; ks++) {
            int kk = ks * 8;
            unsigned a0 = __float_as_uint(As[b][(r0 + g) * AS_S + kk + t4]);
            unsigned a1 = __float_as_uint(As[b][(r0 + g + 8) * AS_S + kk + t4]);
            unsigned a2 = __float_as_uint(As[b][(r0 + g) * AS_S + kk + t4 + 4]);
            unsigned a3 = __float_as_uint(As[b][(r0 + g + 8) * AS_S + kk + t4 + 4]);
#pragma unroll
            for (int s = 0; s < 4; s++) {
                int n = n0 + s * 8 + g;
                unsigned b0 = __float_as_uint(Ws[b][(kk + t4) * WSG_S + n]);
                unsigned b1 = __float_as_uint(Ws[b][(kk + t4 + 4) * WSG_S + n]);
                mma_tf32(acc[s][0], acc[s][1], acc[s][2], acc[s][3],
                         a0, a1, a2, a3, b0, b1);
            }
        }
        if (c + 1 < NC) {
            __syncthreads();
            STORE_CHUNK((c + 1) & 1)
            __syncthreads();
        }
    }

    int gmA = m0 + r0 + g, gmB = gmA + 8;
#pragma unroll
    for (int s = 0; s < 4; s++) {
        int cn = n0 + s * 8 + t4 * 2;
        if (C) {
            if (gmA < M) *(float2*)&C[(size_t)gmA * ldc + cn] = make_float2(acc[s][0], acc[s][1]);
            if (gmB < M) *(float2*)&C[(size_t)gmB * ldc + cn] = make_float2(acc[s][2], acc[s][3]);
        }
        if (Cb) {
            if (gmA < M) *(__nv_bfloat162*)&Cb[(size_t)gmA * ldcb + cn] =
                __float22bfloat162_rn(make_float2(acc[s][0], acc[s][1]));
            if (gmB < M) *(__nv_bfloat162*)&Cb[(size_t)gmB * ldcb + cn] =
                __float22bfloat162_rn(make_float2(acc[s][2], acc[s][3]));
        }
    }
#undef LOAD_CHUNK
#undef STORE_CHUNK
}

__global__ void gemm_tf32(const float* __restrict__ A, int lda,
                          const float* __restrict__ W, int ldw,
                          float* __restrict__ C, int ldc,
                          int M, int Kin, const float* __restrict__ abias) {
    gemm_db_body(A, lda, W, ldw, C + blockIdx.y * 64, ldc, (__nv_bfloat16*)0, 0,
                 M, Kin, blockIdx.x * 64, blockIdx.y * 64, abias);
}

// dual-weight: y=0 -> W0 -> cols [0,64); y=1 -> W1 -> cols [64,128)
__global__ void gemm_tf32_dual(const float* __restrict__ A, int lda,
                               const float* __restrict__ W0, const float* __restrict__ W1,
                               int ldw, float* __restrict__ C,
                               __nv_bfloat16* __restrict__ Cb, int ldc,
                               int M, int Kin, const float* __restrict__ abias) {
    const float* W = blockIdx.y ? W1 : W0;
    gemm_db_body(A, lda, W, ldw, C ? C + blockIdx.y * 64 : (float*)0, ldc,
                 Cb ? Cb + blockIdx.y * 64 : (__nv_bfloat16*)0, ldc,
                 M, Kin, blockIdx.x * 64, 0, abias);
}

// ---------------- scatter-add ----------------
__global__ void scatter_add(const float* __restrict__ M, const int* __restrict__ src,
                            const int* __restrict__ dst, float* __restrict__ A,
                            int nE, int F4) {
    int gt = blockIdx.x * blockDim.x + threadIdx.x;
    int e = gt >> 5, lane = gt & 31;
    if (e >= nE) return;
    int s = src[e], d = dst[e];
    const float4* Mr = (const float4*)&M[(size_t)s * (F4 * 4)];
    float* Ar = &A[(size_t)d * (F4 * 4)];
    for (int c = lane; c < F4; c += 32) {
        float4 v = Mr[c];
        red4(Ar + c * 4, v.x, v.y, v.z, v.w);
    }
}

// ---------------- LayerNorm + ReLU ----------------
__global__ void ln_relu(const float* __restrict__ A, const float* __restrict__ b,
                        const float* __restrict__ g, const float* __restrict__ bt,
                        float* __restrict__ H) {
    int w = (blockIdx.x * blockDim.x + threadIdx.x) >> 5;
    int lane = threadIdx.x & 31;
    if (w >= NN) return;
    float v[8];
    float s = 0.f;
#pragma unroll
    for (int i = 0; i < 8; i++) {
        int j = i * 32 + lane;
        v[i] = A[(size_t)w * 256 + j] + b[j];
        s += v[i];
    }
#pragma unroll
    for (int o = 16; o; o >>= 1) s += __shfl_xor_sync(0xffffffffu, s, o);
    float mu = s * (1.f / 256.f);
    float s2 = 0.f;
#pragma unroll
    for (int i = 0; i < 8; i++) { float d = v[i] - mu; s2 += d * d; }
#pragma unroll
    for (int o = 16; o; o >>= 1) s2 += __shfl_xor_sync(0xffffffffu, s2, o);
    float inv = rsqrtf(s2 * (1.f / 256.f) + LN_EPS);
#pragma unroll
    for (int i = 0; i < 8; i++) {
        int j = i * 32 + lane;
        H[(size_t)w * 256 + j] = fmaxf((v[i] - mu) * inv * g[j] + bt[j], 0.f);
    }
}

// ---------------- z = mu + eps*exp(0.5 lv); KL ----------------
__global__ void z_kl(const float* __restrict__ A2, const float* __restrict__ bmu,
                     const float* __restrict__ blv, const float* __restrict__ eps,
                     float* __restrict__ Z) {
    __shared__ float red[256];
    int idx = blockIdx.x * blockDim.x + threadIdx.x;
    float t = 0.f;
    if (idx < NN * 64) {
        int n = idx >> 6, j = idx & 63;
        float mu = A2[(size_t)n * 128 + j] + bmu[j];
        float lv = A2[(size_t)n * 128 + 64 + j] + blv[j];
        Z[idx] = mu + eps[idx] * expf(0.5f * lv);
        t = 1.f + lv - mu * mu - expf(lv);
    }
    red[threadIdx.x] = t;
    __syncthreads();
    for (int o = 128; o; o >>= 1) {
        if (threadIdx.x < o) red[threadIdx.x] += red[threadIdx.x + o];
        __syncthreads();
    }
    if (threadIdx.x == 0) atomicAdd(&g_acc[0], (double)red[0]);
}

// ---------------- decoder degree / dis ----------------
__global__ void deg_count(const int* __restrict__ pd) {
    int e = blockIdx.x * blockDim.x + threadIdx.x;
    if (e < EP) atomicAdd(&g_deg[pd[e]], 1);
}
__global__ void dis_kernel() {
    int n = blockIdx.x * blockDim.x + threadIdx.x;
    if (n < NN) g_dis[n] = rsqrtf((float)g_deg[n] + 1.0f);
}

// ---------------- normalized scatter ----------------
__global__ void scatter_norm(const float* __restrict__ M, const int* __restrict__ ps,
                             const int* __restrict__ pd, float* __restrict__ A) {
    int idx = blockIdx.x * blockDim.x + threadIdx.x;
    int e = idx >> 4, c = idx & 15;
    if (e >= EP + NN) return;
    int s, d; float coef;
    if (e < EP) { s = ps[e]; d = pd[e]; coef = g_dis[s] * g_dis[d]; }
    else        { s = d = e - EP; float x = g_dis[s]; coef = x * x; }
    float4 v = *(const float4*)&M[(size_t)s * 64 + c * 4];
    red4(&A[(size_t)d * 64 + c * 4], v.x * coef, v.y * coef, v.z * coef, v.w * coef);
}

// ---------------- bias+relu -> bf16 (h for edge gather) ----------------
__global__ void bias_relu_bf16(const float* __restrict__ A, const float* __restrict__ b,
                               __nv_bfloat16* __restrict__ H) {
    int idx = blockIdx.x * blockDim.x + threadIdx.x;
    if (idx < NN * 32) {
        int base = idx * 2;
        float2 v;
        v.x = fmaxf(A[base] + b[base & 63], 0.f);
        v.y = fmaxf(A[base + 1] + b[(base + 1) & 63], 0.f);
        *(__nv_bfloat162*)&H[base] = __float22bfloat162_rn(v);
    }
}

// ---------------- edge MLP + BCE (bf16 m16n8k16, bf16 gathers) ----------------
#define DS2_S 136
#define WS2_S 136
__global__ void edge_mlp_bf16(const __nv_bfloat16* __restrict__ h,
                              const __nv_bfloat16* __restrict__ P,
                              const int* __restrict__ pos, const int* __restrict__ neg,
                              const float* __restrict__ Wa, const float* __restrict__ ba,
                              const float* __restrict__ Wb, const float* __restrict__ bb,
                              const float* __restrict__ tau) {
    extern __shared__ char smraw[];
    float* red  = (float*)smraw;                 // 256
    float* sba  = red + 256;                     // 64
    float* sWb  = sba + 64;                      // 64
    float* slog = sWb + 64;                      // 64
    int*   su   = (int*)(slog + 64);             // 64
    int*   sv   = su + 64;                       // 64
    __nv_bfloat16* Ws2 = (__nv_bfloat16*)(sv + 64);       // [64 n][WS2_S k]
    __nv_bfloat16* Ds2 = Ws2 + 64 * WS2_S;                // [64 e][DS2_S k]

    int t = threadIdx.x;
    int w = t >> 5, lane = t & 31;
    int g = lane >> 2, t4 = lane & 3;
    int r0 = (w & 3) * 16;
    int n0 = (w >> 2) * 32;

    for (int i = t; i < 64 * 128; i += 256) {
        int n = i & 63, k = i >> 6;
        Ws2[n * WS2_S + k] = __float2bfloat16(Wa[(size_t)(128 + k) * 64 + n]);
    }
    if (t < 64) { sba[t] = ba[t]; sWb[t] = Wb[t]; }
    float tau_c = fmaxf(tau[0], 1e-4f);
    float bb0 = bb[0];
    float loc = 0.f;

    const int NTILES = ET / 64;
    for (int tb = blockIdx.x; tb < NTILES; tb += gridDim.x) {
        int e0 = tb * 64;
        __syncthreads();
        if (t < 64) {
            int e = e0 + t;
            if (e < EP) { su[t] = pos[e]; sv[t] = pos[EP + e]; }
            else        { su[t] = neg[e - EP]; sv[t] = neg[EN + (e - EP)]; }
            slog[t] = 0.f;
        }
        __syncthreads();

        // build bf16 feature tile from bf16 h
        {
            int ee = t >> 2, part = t & 3;
            int u = su[ee], v = sv[ee];
            BF8 hu8 = *(const BF8*)&h[(size_t)u * 64 + part * 16];
            BF8 hv8 = *(const BF8*)&h[(size_t)v * 64 + part * 16];
#pragma unroll
            for (int q = 0; q < 8; q++) {
                float2 a = __bfloat1622float2(hu8.p[q]);
                float2 b = __bfloat1622float2(hv8.p[q]);
                int kk = part * 16 + q * 2;
                *(__nv_bfloat162*)&Ds2[ee * DS2_S + kk] =
                    __float22bfloat162_rn(make_float2(fabsf(a.x - b.x), fabsf(a.y - b.y)));
                *(__nv_bfloat162*)&Ds2[ee * DS2_S + 64 + kk] =
                    __float22bfloat162_rn(make_float2(a.x * b.x, a.y * b.y));
            }
        }

        // seed acc with P1[u] + P2[v] (bf16 -> fp32)
        float acc[4][4];
        {
            int uA = su[r0 + g],     vA = sv[r0 + g];
            int uB = su[r0 + g + 8], vB = sv[r0 + g + 8];
#pragma unroll
            for (int s = 0; s < 4; s++) {
                int j0 = n0 + s * 8 + t4 * 2;
                float2 p1 = __bfloat1622float2(*(const __nv_bfloat162*)&P[(size_t)uA * 128 + j0]);
                float2 p2 = __bfloat1622float2(*(const __nv_bfloat162*)&P[(size_t)vA * 128 + 64 + j0]);
                acc[s][0] = p1.x + p2.x; acc[s][1] = p1.y + p2.y;
                float2 q1 = __bfloat1622float2(*(const __nv_bfloat162*)&P[(size_t)uB * 128 + j0]);
                float2 q2 = __bfloat1622float2(*(const __nv_bfloat162*)&P[(size_t)uB == uB ? (size_t)vB * 128 + 64 + j0 : 0]);
                acc[s][2] = q1.x + q2.x; acc[s][3] = q1.y + q2.y;
            }
        }
        __syncthreads();

#pragma unroll
        for (int ks = 0; ks < 8; ks++) {
            int k0 = ks * 16;
            unsigned a0 = *(const unsigned*)&Ds2[(r0 + g) * DS2_S + k0 + t4 * 2];
            unsigned a1 = *(const unsigned*)&Ds2[(r0 + g + 8) * DS2_S + k0 + t4 * 2];
            unsigned a2 = *(const unsigned*)&Ds2[(r0 + g) * DS2_S + k0 + t4 * 2 + 8];
            unsigned a3 = *(const unsigned*)&Ds2[(r0 + g + 8) * DS2_S + k0 + t4 * 2 + 8];
#pragma unroll
            for (int s = 0; s < 4; s++) {
                int n = n0 + s * 8 + g;
                unsigned b0 = *(const unsigned*)&Ws2[n * WS2_S + k0 + t4 * 2];
                unsigned b1 = *(const unsigned*)&Ws2[n * WS2_S + k0 + t4 * 2 + 8];
                mma_bf16(acc[s][0], acc[s][1], acc[s][2], acc[s][3],
                         a0, a1, a2, a3, b0, b1);
            }
        }

        {
            float p_lo = 0.f, p_hi = 0.f;
#pragma unroll
            for (int s = 0; s < 4; s++) {
                int j0 = n0 + s * 8 + t4 * 2;
                p_lo += fmaxf(acc[s][0] + sba[j0], 0.f) * sWb[j0]
                      + fmaxf(acc[s][1] + sba[j0 + 1], 0.f) * sWb[j0 + 1];
                p_hi += fmaxf(acc[s][2] + sba[j0], 0.f) * sWb[j0]
                      + fmaxf(acc[s][3] + sba[j0 + 1], 0.f) * sWb[j0 + 1];
            }
            p_lo += __shfl_down_sync(0xffffffffu, p_lo, 2, 4);
            p_lo += __shfl_down_sync(0xffffffffu, p_lo, 1, 4);
            p_hi += __shfl_down_sync(0xffffffffu, p_hi, 2, 4);
            p_hi += __shfl_down_sync(0xffffffffu, p_hi, 1, 4);
            if (t4 == 0) {
                atomicAdd(&slog[r0 + g], p_lo);
                atomicAdd(&slog[r0 + g + 8], p_hi);
            }
        }
        __syncthreads();

        if (t < 64) {
            float l = (slog[t] + bb0) / tau_c;
            int ge = e0 + t;
            loc += (ge < EP) ? (-5.0f * logsig(l)) : (-logsig(-l));
        }
    }
    __syncthreads();
    red[t] = loc;
    __syncthreads();
    for (int o = 128; o; o >>= 1) {
        if (t < o) red[t] += red[t + o];
        __syncthreads();
    }
    if (t == 0) atomicAdd(&g_acc[1], (double)red[0]);
}

// ---------------- finalize ----------------
__global__ void finalize_k(float* out, int out_size) {
    double kl = -0.5 * g_acc[0] / (double)(NN * 64);
    double recon = g_acc[1] / (double)ET;
    if (out_size >= 3) {
        out[0] = (float)(recon + kl);
        out[1] = (float)recon;
        out[2] = (float)kl;
    } else {
        out[0] = (float)(recon + kl);
    }
}

// ---------------- launch ----------------
extern "C" void kernel_launch(void* const* d_in, const int* in_sizes, int n_in,
                              void* d_out, int out_size) {
    const float* x    = (const float*)d_in[0];
    const float* eps  = (const float*)d_in[1];
    const int* ei     = (const int*)d_in[2];
    const int* pos    = (const int*)d_in[3];
    const int* neg    = (const int*)d_in[4];
    const float* W1   = (const float*)d_in[5];
    const float* b1   = (const float*)d_in[6];
    const float* g1   = (const float*)d_in[7];
    const float* bt1  = (const float*)d_in[8];
    const float* Wmu  = (const float*)d_in[9];
    const float* bmu  = (const float*)d_in[10];
    const float* Wlv  = (const float*)d_in[11];
    const float* blv  = (const float*)d_in[12];
    const float* Wd1  = (const float*)d_in[13];
    const float* bd1  = (const float*)d_in[14];
    const float* Wd2  = (const float*)d_in[15];
    const float* bd2  = (const float*)d_in[16];
    const float* Wa   = (const float*)d_in[17];
    const float* ba   = (const float*)d_in[18];
    const float* Wb   = (const float*)d_in[19];
    const float* bb   = (const float*)d_in[20];
    const float* tau  = (const float*)d_in[21];
    float* out = (float*)d_out;

    const int* src = ei;
    const int* dst = ei + E2;
    const int* ps  = pos;
    const int* pd  = pos + EP;

    float *M1, *A1, *H1, *M2, *A2, *Z, *M3, *A3a, *A3b;
    __nv_bfloat16 *Hbf, *Pbf;
    cudaGetSymbolAddress((void**)&M1, g_M1);
    cudaGetSymbolAddress((void**)&A1, g_A1);
    cudaGetSymbolAddress((void**)&H1, g_H1);
    cudaGetSymbolAddress((void**)&M2, g_M2);
    cudaGetSymbolAddress((void**)&A2, g_A2);
    cudaGetSymbolAddress((void**)&Z,  g_Z);
    cudaGetSymbolAddress((void**)&M3, g_M3);
    cudaGetSymbolAddress((void**)&A3a, g_A3a);
    cudaGetSymbolAddress((void**)&A3b, g_A3b);
    cudaGetSymbolAddress((void**)&Hbf, g_Hbf);
    cudaGetSymbolAddress((void**)&Pbf, g_Pbf);

    const int EDGE_SMEM = (256 + 64 * 3) * 4 + 128 * 4 + (64 * WS2_S + 64 * DS2_S) * 2;
    cudaFuncSetAttribute(edge_mlp_bf16, cudaFuncAttributeMaxDynamicSharedMemorySize, EDGE_SMEM);

    zero_all<<<2048, 256>>>();

    const int GM = (NN + 63) / 64;   // 313
    gemm_tf32<<<dim3(GM, 4), 256>>>(x, 256, W1, 256, M1, 256, NN, 256, nullptr);

    scatter_add<<<(E2 * 32 + 255) / 256, 256>>>(M1, src, dst, A1, E2, 64);
    ln_relu<<<(NN * 32 + 255) / 256, 256>>>(A1, b1, g1, bt1, H1);

    gemm_tf32_dual<<<dim3(GM, 2), 256>>>(H1, 256, Wmu, Wlv, 64, M2, nullptr, 128, NN, 256, nullptr);
    scatter_add<<<(E2 * 32 + 255) / 256, 256>>>(M2, src, dst, A2, E2, 32);
    z_kl<<<(NN * 64 + 255) / 256, 256>>>(A2, bmu, blv, eps, Z);

    deg_count<<<(EP + 255) / 256, 256>>>(pd);
    dis_kernel<<<(NN + 255) / 256, 256>>>();

    gemm_tf32<<<dim3(GM, 1), 256>>>(Z, 64, Wd1, 64, M3, 64, NN, 64, nullptr);
    scatter_norm<<<((EP + NN) * 16 + 255) / 256, 256>>>(M3, ps, pd, A3a);

    // pass 2: A = relu(A3a + bd1) fused into GEMM
    gemm_tf32<<<dim3(GM, 1), 256>>>(A3a, 64, Wd2, 64, M3, 64, NN, 64, bd1);
    scatter_norm<<<((EP + NN) * 16 + 255) / 256, 256>>>(M3, ps, pd, A3b);

    // h (bf16) and P (bf16) from A3b with bd2+relu fused
    bias_relu_bf16<<<(NN * 32 + 255) / 256, 256>>>(A3b, bd2, Hbf);
    gemm_tf32_dual<<<dim3(GM, 2), 256>>>(A3b, 64, Wa, Wa + 64 * 64, 64,
                                         nullptr, Pbf, 128, NN, 64, bd2);

    edge_mlp_bf16<<<592, 256, EDGE_SMEM>>>(Hbf, Pbf, pos, neg, Wa, ba, Wb, bb, tau);

    finalize_k<<<1, 1>>>(out, out_size);
}